// round 12
// baseline (speedup 1.0000x reference)
#include <cuda_runtime.h>
#include <cstdint>

// ---------------------------------------------------------------------------
// Problem constants
//   feat0_c, feat1_c : [2,128,32,32] fp32
//   feat0_f, feat1_f : [2,128,64,64] fp32
// ---------------------------------------------------------------------------

static const size_t OFF_TF    = 0;
static const size_t OFF_TFC   = 2097152;
static const size_t OFF_C     = 4194304;
static const size_t OFF_CF    = 37748736;
static const size_t OFF_FLOW  = 71303168;
static const size_t OFF_FLOWF = 71319552;

// Scratch (device globals — no allocation allowed)
__device__ float g_cc[2 * 1024 * 1024];          // corr_c  [b][p0c][p1c]   8 MB
__device__ float g_i1[2 * 1024 * 4096];          // (u,v)-upsampled corr_c  33.5 MB (L2-resident)

// softargmax tile partials: rows -> flow, cols -> flow_flip
// row partials: [col-tile j(32)][b(2)][row t(4096)]; col partials: [row-tile][b][col]
__device__ float g_r_mx[32 * 2 * 4096];
__device__ float g_r_z [32 * 2 * 4096];
__device__ float g_r_sx[32 * 2 * 4096];
__device__ float g_r_sy[32 * 2 * 4096];
__device__ float g_c_mx[32 * 2 * 4096];
__device__ float g_c_z [32 * 2 * 4096];
__device__ float g_c_sx[32 * 2 * 4096];
__device__ float g_c_sy[32 * 2 * 4096];

// ---------------------------------------------------------------------------
// helpers
// ---------------------------------------------------------------------------
__device__ __forceinline__ uint32_t pack_bf16x2(float hi, float lo) {
    uint32_t r;
    asm("cvt.rn.bf16x2.f32 %0, %1, %2;" : "=r"(r) : "f"(hi), "f"(lo));
    return r;
}

__device__ __forceinline__ void mma_bf16(float* d, const uint32_t* a, const uint32_t* b) {
    asm volatile(
        "mma.sync.aligned.m16n8k16.row.col.f32.bf16.bf16.f32 "
        "{%0,%1,%2,%3}, {%4,%5,%6,%7}, {%8,%9}, {%0,%1,%2,%3};\n"
        : "+f"(d[0]), "+f"(d[1]), "+f"(d[2]), "+f"(d[3])
        : "r"(a[0]), "r"(a[1]), "r"(a[2]), "r"(a[3]), "r"(b[0]), "r"(b[1]));
}

__device__ __forceinline__ void ldsm_x4(uint32_t* r, uint32_t saddr) {
    asm volatile("ldmatrix.sync.aligned.m8n8.x4.shared.b16 {%0,%1,%2,%3}, [%4];"
                 : "=r"(r[0]), "=r"(r[1]), "=r"(r[2]), "=r"(r[3]) : "r"(saddr));
}

__device__ __forceinline__ void lerp_weights(int i, int& i0, int& i1, float& w) {
    float f = (float)(i * 31) / 63.0f;   // align_corners scale 31/63, exact at i=0,63
    i0 = (int)f;
    w  = f - (float)i0;
    i1 = min(i0 + 1, 31);
}

__device__ __forceinline__ float warp_max(float v) {
#pragma unroll
    for (int o = 16; o; o >>= 1) v = fmaxf(v, __shfl_xor_sync(0xffffffffu, v, o));
    return v;
}
__device__ __forceinline__ float warp_sum(float v) {
#pragma unroll
    for (int o = 16; o; o >>= 1) v += __shfl_xor_sync(0xffffffffu, v, o);
    return v;
}

// ---------------------------------------------------------------------------
// Correlation GEMM (bf16x3, near-fp32 accuracy), 256 threads / 8 warps,
// 2 CTAs per SM. Block tile 128(m) x 64(n), warp tile 32x32, BK=16,
// mma.m16n8k16 + ldmatrix.x4, double-buffered smem.
// FUSE epilogue: c = 0.5*(rowinterp(g_i1) + corr), writes c + c_flip.
// ---------------------------------------------------------------------------
template <int MT, bool FUSE>
__global__ __launch_bounds__(256, 2)
void gemm_corr_kernel(const float* __restrict__ f0, const float* __restrict__ f1,
                      float* __restrict__ outC, float* __restrict__ outF)
{
    extern __shared__ uint32_t smemw[];

    const int b  = blockIdx.z;
    const int m0 = blockIdx.y * 128;
    const int n0 = blockIdx.x * 64;
    const float* A  = f0 + (size_t)b * 128 * MT;  // [K=128][MT]
    const float* Bg = f1 + (size_t)b * 128 * MT;

    const int tid  = threadIdx.x;
    const int warp = tid >> 5, lane = tid & 31;
    const int gid  = lane >> 2, tig = lane & 3;
    const int wm0  = (warp >> 1) * 32;           // 4 warp rows
    const int wn0  = (warp & 1) * 32;            // 2 warp cols

    float acc[2][4][4];
#pragma unroll
    for (int mi = 0; mi < 2; mi++)
#pragma unroll
        for (int j = 0; j < 4; j++)
#pragma unroll
            for (int r = 0; r < 4; r++) acc[mi][j][r] = 0.0f;

    // ---- producer mapping ----
    const int colA = tid & 127;
    const int kgA  = tid >> 7;                   // 0..1
    const int colB = tid & 63;
    const int kgB  = tid >> 6;                   // 0..3

    const uint32_t sbase = (uint32_t)__cvta_generic_to_shared(smemw);

    // ---- consumer ldmatrix row offsets (word units) ----
    const int Lm = lane & 7;
    const int mrowA = ((lane >> 3) & 1) * 8 + Lm;
    const int koffA = (lane >> 4) * 4;
    const uint32_t aoff0 = (uint32_t)((wm0 + mrowA) * 20 + koffA);
    const uint32_t aoff1 = (uint32_t)((wm0 + 16 + mrowA) * 20 + koffA);
    const int nrowB = Lm + ((lane >> 4) << 3);
    const int koffB = ((lane >> 3) & 1) * 4;
    const uint32_t boff0 = (uint32_t)(2560 + (wn0 + nrowB) * 20 + koffB);
    const uint32_t boff1 = (uint32_t)(2560 + (wn0 + 16 + nrowB) * 20 + koffB);

    float a0v0, a0v1, a0v2, a0v3;
    float a1v0, a1v1, a1v2, a1v3;
    float bv0, bv1, bv2, bv3;

#define LOAD_CHUNK(kb)                                                               \
    do {                                                                             \
        const float* Ar0 = A + (size_t)((kb) * 16 + kgA * 4) * MT + m0 + colA;       \
        const float* Ar1 = A + (size_t)((kb) * 16 + (kgA + 2) * 4) * MT + m0 + colA; \
        const float* Br  = Bg + (size_t)((kb) * 16 + kgB * 4) * MT + n0 + colB;      \
        a0v0 = Ar0[0]; a0v1 = Ar0[MT]; a0v2 = Ar0[2 * (size_t)MT]; a0v3 = Ar0[3 * (size_t)MT]; \
        a1v0 = Ar1[0]; a1v1 = Ar1[MT]; a1v2 = Ar1[2 * (size_t)MT]; a1v3 = Ar1[3 * (size_t)MT]; \
        bv0  = Br[0];  bv1  = Br[MT];  bv2  = Br[2 * (size_t)MT];  bv3  = Br[3 * (size_t)MT];  \
    } while (0)

#define PACK_STORE(base_w, v0, v1, v2, v3)                                           \
    do {                                                                             \
        uint32_t h0 = pack_bf16x2(v1, v0);                                           \
        uint32_t h1 = pack_bf16x2(v3, v2);                                           \
        uint32_t l0 = pack_bf16x2(v1 - __uint_as_float(h0 & 0xffff0000u),            \
                                  v0 - __uint_as_float(h0 << 16));                   \
        uint32_t l1 = pack_bf16x2(v3 - __uint_as_float(h1 & 0xffff0000u),            \
                                  v2 - __uint_as_float(h1 << 16));                   \
        *reinterpret_cast<uint2*>(&smemw[(base_w)])     = make_uint2(h0, h1);        \
        *reinterpret_cast<uint2*>(&smemw[(base_w) + 8]) = make_uint2(l0, l1);        \
    } while (0)

#define STORE_CHUNK(bufw)                                                            \
    do {                                                                             \
        PACK_STORE((bufw) + colA * 20 + 2 * kgA,       a0v0, a0v1, a0v2, a0v3);      \
        PACK_STORE((bufw) + colA * 20 + 2 * (kgA + 2), a1v0, a1v1, a1v2, a1v3);      \
        PACK_STORE((bufw) + 2560 + colB * 20 + 2 * kgB, bv0, bv1, bv2, bv3);         \
    } while (0)

    LOAD_CHUNK(0);
    STORE_CHUNK(0u);
    __syncthreads();

    for (int kb = 0; kb < 8; kb++) {
        if (kb < 7) LOAD_CHUNK(kb + 1);           // global prefetch (hidden by MMA)

        const uint32_t bw = (uint32_t)(kb & 1) * 3840u;
        uint32_t bh[2][4], bl[2][4];
        ldsm_x4(bh[0], sbase + (bw + boff0) * 4u);
        ldsm_x4(bl[0], sbase + (bw + boff0 + 8u) * 4u);
        ldsm_x4(bh[1], sbase + (bw + boff1) * 4u);
        ldsm_x4(bl[1], sbase + (bw + boff1 + 8u) * 4u);

#pragma unroll
        for (int mi = 0; mi < 2; mi++) {
            uint32_t ah[4], al[4];
            const uint32_t ao = (mi ? aoff1 : aoff0);
            ldsm_x4(ah, sbase + (bw + ao) * 4u);
            ldsm_x4(al, sbase + (bw + ao + 8u) * 4u);
#pragma unroll
            for (int j = 0; j < 4; j++) {
                const uint32_t* bfh = &bh[j >> 1][(j & 1) * 2];
                const uint32_t* bfl = &bl[j >> 1][(j & 1) * 2];
                mma_bf16(acc[mi][j], al, bfh);   // lo*hi
                mma_bf16(acc[mi][j], ah, bfl);   // hi*lo
                mma_bf16(acc[mi][j], ah, bfh);   // hi*hi
            }
        }

        if (kb < 7) STORE_CHUNK((uint32_t)((kb + 1) & 1) * 3840u);
        __syncthreads();
    }
#undef LOAD_CHUNK
#undef PACK_STORE
#undef STORE_CHUNK

    const float sc = 0.08838834764831845f;       // 1/sqrt(128)

    if constexpr (!FUSE) {
        // coarse: write scaled correlation to g_cc
        float* out = g_cc + (size_t)b * MT * MT;
        (void)outC; (void)outF;
#pragma unroll
        for (int mi = 0; mi < 2; mi++)
#pragma unroll
            for (int j = 0; j < 4; j++) {
                int r0 = m0 + wm0 + mi * 16 + gid;
                int cc = n0 + wn0 + j * 8 + 2 * tig;
                float2 v0 = make_float2(acc[mi][j][0] * sc, acc[mi][j][1] * sc);
                float2 v1 = make_float2(acc[mi][j][2] * sc, acc[mi][j][3] * sc);
                *reinterpret_cast<float2*>(&out[(size_t)r0 * MT + cc])       = v0;
                *reinterpret_cast<float2*>(&out[(size_t)(r0 + 8) * MT + cc]) = v1;
            }
    } else {
        // fine: c = 0.5*(rowinterp + corr), plus transposed write for c_flip
        float* S = reinterpret_cast<float*>(smemw);        // 128 x 65 (33.3 KB)
        float* Y = reinterpret_cast<float*>(smemw) + 8320; // 64 x 68  (17.4 KB)
        const size_t cb = (size_t)b * MT * MT;
        const int h0base = m0 >> 6;               // two h0 values: h0base, h0base+1

        // --- store corr into S (all 8 warps cover 128x64 disjointly) ---
#pragma unroll
        for (int mi = 0; mi < 2; mi++)
#pragma unroll
            for (int j = 0; j < 4; j++) {
                int r0  = wm0 + mi * 16 + gid;
                int col = wn0 + j * 8 + 2 * tig;
                S[r0 * 65 + col]           = acc[mi][j][0] * sc;
                S[r0 * 65 + col + 1]       = acc[mi][j][1] * sc;
                S[(r0 + 8) * 65 + col]     = acc[mi][j][2] * sc;
                S[(r0 + 8) * 65 + col + 1] = acc[mi][j][3] * sc;
            }

        // --- build Y: y-blend of g_i1 rows for 2 h0 values, 32 cx, 64 cols ---
#pragma unroll
        for (int t = 0; t < 4; t++) {
            int e     = tid + t * 256;            // 0..1023
            int h0loc = e >> 9;
            int cx    = (e >> 4) & 31;
            int c4    = e & 15;
            int y0, y1; float wy;
            lerp_weights(h0base + h0loc, y0, y1, wy);
            const float4* p0 = reinterpret_cast<const float4*>(
                g_i1 + ((size_t)b * 1024 + y0 * 32 + cx) * 4096 + n0) + c4;
            const float4* p1 = reinterpret_cast<const float4*>(
                g_i1 + ((size_t)b * 1024 + y1 * 32 + cx) * 4096 + n0) + c4;
            float4 a = *p0, bb = *p1;
            float4 v;
            v.x = a.x + wy * (bb.x - a.x);
            v.y = a.y + wy * (bb.y - a.y);
            v.z = a.z + wy * (bb.z - a.z);
            v.w = a.w + wy * (bb.w - a.w);
            *reinterpret_cast<float4*>(&Y[(h0loc * 32 + cx) * 68 + c4 * 4]) = v;
        }
        __syncthreads();

        // --- combine: x-blend + corr, write c, keep combined in S ---
#pragma unroll
        for (int q = 0; q < 8; q++) {
            int idx = tid + q * 256;              // float4 units over 128x64
            int r   = idx >> 4;
            int cf  = (idx & 15) << 2;
            int h0loc = r >> 6;
            int w0    = r & 63;
            int x0, x1; float wx;
            lerp_weights(w0, x0, x1, wx);
            float4 ya = *reinterpret_cast<const float4*>(&Y[(h0loc * 32 + x0) * 68 + cf]);
            float4 yb = *reinterpret_cast<const float4*>(&Y[(h0loc * 32 + x1) * 68 + cf]);
            float4 ip;
            ip.x = ya.x + wx * (yb.x - ya.x);
            ip.y = ya.y + wx * (yb.y - ya.y);
            ip.z = ya.z + wx * (yb.z - ya.z);
            ip.w = ya.w + wx * (yb.w - ya.w);
            size_t ga = cb + (size_t)(m0 + r) * MT + n0 + cf;
            float4 v;
            v.x = 0.5f * (ip.x + S[r * 65 + cf]);
            v.y = 0.5f * (ip.y + S[r * 65 + cf + 1]);
            v.z = 0.5f * (ip.z + S[r * 65 + cf + 2]);
            v.w = 0.5f * (ip.w + S[r * 65 + cf + 3]);
            *reinterpret_cast<float4*>(outC + ga) = v;
            S[r * 65 + cf]     = v.x;             // keep combined value for flip write
            S[r * 65 + cf + 1] = v.y;
            S[r * 65 + cf + 2] = v.z;
            S[r * 65 + cf + 3] = v.w;
        }
        __syncthreads();

        // --- transposed rows: c_flip[n][m0..m0+127] ---
#pragma unroll
        for (int jr = 0; jr < 8; jr++) {
            int n = warp * 8 + jr;
            size_t fb = cb + (size_t)(n0 + n) * MT + m0;
#pragma unroll
            for (int q = 0; q < 4; q++) {
                int m = lane + q * 32;            // bank = (m+n)%32 -> conflict-free
                outF[fb + m] = S[m * 65 + n];
            }
        }
    }
}

// ---------------------------------------------------------------------------
// trans_features_coarse: bilinear 32->64 (align_corners) per channel
// ---------------------------------------------------------------------------
__global__ __launch_bounds__(256)
void resize_coarse_kernel(const float* __restrict__ a, const float* __restrict__ bsrc,
                          float* __restrict__ out)
{
    __shared__ float s[1024];
    int blk = blockIdx.x;                        // 0..511
    int bb = blk >> 8, ii = (blk >> 7) & 1, ch = blk & 127;
    const float* in = (ii ? bsrc : a) + ((size_t)bb * 128 + ch) * 1024;
    float* o = out + (((size_t)bb * 2 + ii) * 128 + ch) * 4096;
    int tid = threadIdx.x;
#pragma unroll
    for (int q = 0; q < 4; q++) s[tid + q * 256] = in[tid + q * 256];
    __syncthreads();
#pragma unroll
    for (int q = 0; q < 16; q++) {
        int oi = tid + q * 256;
        int oy = oi >> 6, ox = oi & 63;
        int y0, y1, x0, x1; float wy, wx;
        lerp_weights(oy, y0, y1, wy);
        lerp_weights(ox, x0, x1, wx);
        float v = (1.0f - wy) * ((1.0f - wx) * s[y0 * 32 + x0] + wx * s[y0 * 32 + x1])
                +         wy  * ((1.0f - wx) * s[y1 * 32 + x0] + wx * s[y1 * 32 + x1]);
        o[oi] = v;
    }
}

// ---------------------------------------------------------------------------
// interp pass A: per (b,p0c) row, upsample (u,v) 32x32 -> 64x64
// ---------------------------------------------------------------------------
__global__ __launch_bounds__(256)
void interpA_kernel()
{
    __shared__ float s[1024];
    int blk = blockIdx.x;                        // 0..2047 = b*1024 + p0c
    const float* in = g_cc + (size_t)blk * 1024;
    float* o = g_i1 + (size_t)blk * 4096;
    int tid = threadIdx.x;
#pragma unroll
    for (int q = 0; q < 4; q++) s[tid + q * 256] = in[tid + q * 256];
    __syncthreads();
#pragma unroll
    for (int q = 0; q < 16; q++) {
        int oi = tid + q * 256;
        int oy = oi >> 6, ox = oi & 63;
        int y0, y1, x0, x1; float wy, wx;
        lerp_weights(oy, y0, y1, wy);
        lerp_weights(ox, x0, x1, wx);
        float v = (1.0f - wy) * ((1.0f - wx) * s[y0 * 32 + x0] + wx * s[y0 * 32 + x1])
                +         wy  * ((1.0f - wx) * s[y1 * 32 + x0] + wx * s[y1 * 32 + x1]);
        o[oi] = v;
    }
}

// ---------------------------------------------------------------------------
// softargmax tile pass over c ONLY (single 134MB DRAM read for BOTH flows):
//   grid (32, 32, 2): 128x128 tile of c; indices reversed for L2 harvest.
//   Row pass: warp-per-16-rows, global->regs, per-row {max,Z,Sx,Sy} via shfl;
//             values stashed in smem (stride 129 -> conflict-free).
//   Col pass: 2 threads per column scan 64 smem rows online; halves merged.
// ---------------------------------------------------------------------------
__global__ __launch_bounds__(256, 2)
void softargmax_tile_kernel(const float* __restrict__ c)
{
    extern __shared__ float S[];                 // 128 x 129
    const int bx = 31 - (int)blockIdx.x;         // col tile
    const int by = 31 - (int)blockIdx.y;         // row tile
    const int b  = 1 - (int)blockIdx.z;
    const int r0 = by * 128, c0 = bx * 128;
    const int tid = threadIdx.x, lane = tid & 31, warp = tid >> 5;
    const float inv = 2.0f / 63.0f;

    // ---- row pass ----
    for (int rr = 0; rr < 16; rr++) {
        const int row  = warp * 16 + rr;
        const int grow = r0 + row;
        const float* rp = c + ((size_t)b * 4096 + grow) * 4096 + c0;
        float v[4];
#pragma unroll
        for (int e = 0; e < 4; e++) v[e] = rp[e * 32 + lane];
#pragma unroll
        for (int e = 0; e < 4; e++) S[row * 129 + e * 32 + lane] = v[e];

        float mx = fmaxf(fmaxf(v[0], v[1]), fmaxf(v[2], v[3]));
        mx = warp_max(mx);
        float Z = 0.0f, Sx = 0.0f, Sy = 0.0f;
#pragma unroll
        for (int e = 0; e < 4; e++) {
            float d = (v[e] - mx) * 50.0f;
            if (d > -25.0f) {
                float ee = __expf(d);
                int j = c0 + e * 32 + lane;
                Z  += ee;
                Sx += ee * ((float)(j & 63) * inv - 1.0f);
                Sy += ee * ((float)(j >> 6) * inv - 1.0f);
            }
        }
        Z = warp_sum(Z); Sx = warp_sum(Sx); Sy = warp_sum(Sy);
        if (lane == 0) {
            size_t p = ((size_t)bx * 2 + b) * 4096 + grow;
            g_r_mx[p] = mx; g_r_z[p] = Z; g_r_sx[p] = Sx; g_r_sy[p] = Sy;
        }
    }
    __syncthreads();

    // ---- col pass (online over 64 smem rows per thread) ----
    const int colc = tid & 127, half = tid >> 7;
    float M = -1e30f, Z = 0.0f, Sx = 0.0f, Sy = 0.0f;
    for (int rr = 0; rr < 64; rr++) {
        int row = half * 64 + rr;
        float vv = S[row * 129 + colc];
        int m = r0 + row;
        float xn = (float)(m & 63) * inv - 1.0f;
        float yn = (float)(m >> 6) * inv - 1.0f;
        if (vv > M) {
            float s = __expf((M - vv) * 50.0f);
            Z = Z * s + 1.0f; Sx = Sx * s + xn; Sy = Sy * s + yn; M = vv;
        } else {
            float d = (vv - M) * 50.0f;
            if (d > -25.0f) { float ee = __expf(d); Z += ee; Sx += ee * xn; Sy += ee * yn; }
        }
    }
    __shared__ float M2[128], Z2[128], X2[128], Y2[128];
    if (half == 1) { M2[colc] = M; Z2[colc] = Z; X2[colc] = Sx; Y2[colc] = Sy; }
    __syncthreads();
    if (half == 0) {
        float m2 = M2[colc], z2 = Z2[colc], x2 = X2[colc], y2 = Y2[colc];
        if (m2 > M) {
            float s = __expf((M - m2) * 50.0f);
            Z = Z * s + z2; Sx = Sx * s + x2; Sy = Sy * s + y2; M = m2;
        } else {
            float s = __expf((m2 - M) * 50.0f);
            Z += z2 * s; Sx += x2 * s; Sy += y2 * s;
        }
        size_t p = ((size_t)by * 2 + b) * 4096 + c0 + colc;
        g_c_mx[p] = M; g_c_z[p] = Z; g_c_sx[p] = Sx; g_c_sy[p] = Sy;
    }
}

// ---------------------------------------------------------------------------
// flow reduce: online merge of 32 tile partials per target.
// grid (16, 2, 2): t = x*256+tid, b = y, z: 0 = rows->flow, 1 = cols->flow_flip
// ---------------------------------------------------------------------------
__global__ __launch_bounds__(256)
void flow_reduce_kernel(float* __restrict__ fl, float* __restrict__ flf)
{
    const int t = blockIdx.x * 256 + threadIdx.x;
    const int b = blockIdx.y;
    const bool rows = (blockIdx.z == 0);
    const float* pmx = rows ? g_r_mx : g_c_mx;
    const float* pz  = rows ? g_r_z  : g_c_z;
    const float* psx = rows ? g_r_sx : g_c_sx;
    const float* psy = rows ? g_r_sy : g_c_sy;
    float* outp = rows ? fl : flf;

    float M = -1e30f, Z = 0.0f, Sx = 0.0f, Sy = 0.0f;
    for (int j = 0; j < 32; j++) {
        size_t idx = ((size_t)j * 2 + b) * 4096 + t;
        float mj = pmx[idx], zj = pz[idx], sxj = psx[idx], syj = psy[idx];
        if (mj > M) {
            float s = __expf((M - mj) * 50.0f);
            Z *= s; Sx *= s; Sy *= s; M = mj;
        }
        float w = __expf((mj - M) * 50.0f);
        Z += w * zj; Sx += w * sxj; Sy += w * syj;
    }
    float gx = Sx / Z, gy = Sy / Z;
    float w = (float)(t & 63), h = (float)(t >> 6);
    outp[(size_t)b * 8192 + t]        = (gx + 1.0f) * 31.5f - w;
    outp[(size_t)b * 8192 + 4096 + t] = (gy + 1.0f) * 31.5f - h;
}

// ---------------------------------------------------------------------------
// launch
// ---------------------------------------------------------------------------
extern "C" void kernel_launch(void* const* d_in, const int* in_sizes, int n_in,
                              void* d_out, int out_size)
{
    (void)in_sizes; (void)n_in; (void)out_size;
    const float* f0c = (const float*)d_in[0];
    const float* f1c = (const float*)d_in[1];
    const float* f0f = (const float*)d_in[2];
    const float* f1f = (const float*)d_in[3];
    float* out = (float*)d_out;

    cudaFuncSetAttribute(gemm_corr_kernel<4096, true>,
                         cudaFuncAttributeMaxDynamicSharedMemorySize, 50688);
    cudaFuncSetAttribute(softargmax_tile_kernel,
                         cudaFuncAttributeMaxDynamicSharedMemorySize, 66048);

    // trans_features = stack([feat0_f, feat1_f], axis=1)
    const size_t chunk = (size_t)128 * 4096;
    cudaMemcpyAsync(out + OFF_TF + 0 * chunk, f0f,         chunk * 4, cudaMemcpyDeviceToDevice, 0);
    cudaMemcpyAsync(out + OFF_TF + 1 * chunk, f1f,         chunk * 4, cudaMemcpyDeviceToDevice, 0);
    cudaMemcpyAsync(out + OFF_TF + 2 * chunk, f0f + chunk, chunk * 4, cudaMemcpyDeviceToDevice, 0);
    cudaMemcpyAsync(out + OFF_TF + 3 * chunk, f1f + chunk, chunk * 4, cudaMemcpyDeviceToDevice, 0);

    resize_coarse_kernel<<<512, 256>>>(f0c, f1c, out + OFF_TFC);

    gemm_corr_kernel<1024, false><<<dim3(16, 8, 2), 256, 30720>>>(f0c, f1c, nullptr, nullptr);
    interpA_kernel<<<2048, 256>>>();
    gemm_corr_kernel<4096, true><<<dim3(64, 32, 2), 256, 50688>>>(f0f, f1f, out + OFF_C, out + OFF_CF);

    softargmax_tile_kernel<<<dim3(32, 32, 2), 256, 66048>>>(out + OFF_C);
    flow_reduce_kernel<<<dim3(16, 2, 2), 256>>>(out + OFF_FLOW, out + OFF_FLOWF);
}

// round 13
// speedup vs baseline: 1.1153x; 1.1153x over previous
#include <cuda_runtime.h>
#include <cstdint>

// ---------------------------------------------------------------------------
// Problem constants
//   feat0_c, feat1_c : [2,128,32,32] fp32
//   feat0_f, feat1_f : [2,128,64,64] fp32
// ---------------------------------------------------------------------------

static const size_t OFF_TF    = 0;
static const size_t OFF_TFC   = 2097152;
static const size_t OFF_C     = 4194304;
static const size_t OFF_CF    = 37748736;
static const size_t OFF_FLOW  = 71303168;
static const size_t OFF_FLOWF = 71319552;

// Scratch (device globals — no allocation allowed)
__device__ float g_cc[2 * 1024 * 1024];          // corr_c  [b][p0c][p1c]   8 MB
__device__ float g_i1[2 * 1024 * 4096];          // (u,v)-upsampled corr_c  33.5 MB (L2-resident)

// ---------------------------------------------------------------------------
// helpers
// ---------------------------------------------------------------------------
__device__ __forceinline__ uint32_t pack_bf16x2(float hi, float lo) {
    uint32_t r;
    asm("cvt.rn.bf16x2.f32 %0, %1, %2;" : "=r"(r) : "f"(hi), "f"(lo));
    return r;
}

__device__ __forceinline__ void mma_bf16(float* d, const uint32_t* a, const uint32_t* b) {
    asm volatile(
        "mma.sync.aligned.m16n8k16.row.col.f32.bf16.bf16.f32 "
        "{%0,%1,%2,%3}, {%4,%5,%6,%7}, {%8,%9}, {%0,%1,%2,%3};\n"
        : "+f"(d[0]), "+f"(d[1]), "+f"(d[2]), "+f"(d[3])
        : "r"(a[0]), "r"(a[1]), "r"(a[2]), "r"(a[3]), "r"(b[0]), "r"(b[1]));
}

__device__ __forceinline__ void ldsm_x4(uint32_t* r, uint32_t saddr) {
    asm volatile("ldmatrix.sync.aligned.m8n8.x4.shared.b16 {%0,%1,%2,%3}, [%4];"
                 : "=r"(r[0]), "=r"(r[1]), "=r"(r[2]), "=r"(r[3]) : "r"(saddr));
}

__device__ __forceinline__ void lerp_weights(int i, int& i0, int& i1, float& w) {
    float f = (float)(i * 31) / 63.0f;   // align_corners scale 31/63, exact at i=0,63
    i0 = (int)f;
    w  = f - (float)i0;
    i1 = min(i0 + 1, 31);
}

// ---------------------------------------------------------------------------
// Correlation GEMM (bf16x3, near-fp32 accuracy), 256 threads / 8 warps,
// 2 CTAs per SM. Block tile 128(m) x 64(n), warp tile 32x32, BK=16,
// mma.m16n8k16 + ldmatrix.x4, double-buffered smem.
// FUSE epilogue: c = 0.5*(rowinterp(g_i1) + corr), writes c + c_flip.
// ---------------------------------------------------------------------------
template <int MT, bool FUSE>
__global__ __launch_bounds__(256, 2)
void gemm_corr_kernel(const float* __restrict__ f0, const float* __restrict__ f1,
                      float* __restrict__ outC, float* __restrict__ outF)
{
    extern __shared__ uint32_t smemw[];

    const int b  = blockIdx.z;
    const int m0 = blockIdx.y * 128;
    const int n0 = blockIdx.x * 64;
    const float* A  = f0 + (size_t)b * 128 * MT;  // [K=128][MT]
    const float* Bg = f1 + (size_t)b * 128 * MT;

    const int tid  = threadIdx.x;
    const int warp = tid >> 5, lane = tid & 31;
    const int gid  = lane >> 2, tig = lane & 3;
    const int wm0  = (warp >> 1) * 32;           // 4 warp rows
    const int wn0  = (warp & 1) * 32;            // 2 warp cols

    float acc[2][4][4];
#pragma unroll
    for (int mi = 0; mi < 2; mi++)
#pragma unroll
        for (int j = 0; j < 4; j++)
#pragma unroll
            for (int r = 0; r < 4; r++) acc[mi][j][r] = 0.0f;

    // ---- producer mapping ----
    const int colA = tid & 127;
    const int kgA  = tid >> 7;                   // 0..1
    const int colB = tid & 63;
    const int kgB  = tid >> 6;                   // 0..3

    const uint32_t sbase = (uint32_t)__cvta_generic_to_shared(smemw);

    // ---- consumer ldmatrix row offsets (word units) ----
    const int Lm = lane & 7;
    const int mrowA = ((lane >> 3) & 1) * 8 + Lm;
    const int koffA = (lane >> 4) * 4;
    const uint32_t aoff0 = (uint32_t)((wm0 + mrowA) * 20 + koffA);
    const uint32_t aoff1 = (uint32_t)((wm0 + 16 + mrowA) * 20 + koffA);
    const int nrowB = Lm + ((lane >> 4) << 3);
    const int koffB = ((lane >> 3) & 1) * 4;
    const uint32_t boff0 = (uint32_t)(2560 + (wn0 + nrowB) * 20 + koffB);
    const uint32_t boff1 = (uint32_t)(2560 + (wn0 + 16 + nrowB) * 20 + koffB);

    float a0v0, a0v1, a0v2, a0v3;
    float a1v0, a1v1, a1v2, a1v3;
    float bv0, bv1, bv2, bv3;

#define LOAD_CHUNK(kb)                                                               \
    do {                                                                             \
        const float* Ar0 = A + (size_t)((kb) * 16 + kgA * 4) * MT + m0 + colA;       \
        const float* Ar1 = A + (size_t)((kb) * 16 + (kgA + 2) * 4) * MT + m0 + colA; \
        const float* Br  = Bg + (size_t)((kb) * 16 + kgB * 4) * MT + n0 + colB;      \
        a0v0 = Ar0[0]; a0v1 = Ar0[MT]; a0v2 = Ar0[2 * (size_t)MT]; a0v3 = Ar0[3 * (size_t)MT]; \
        a1v0 = Ar1[0]; a1v1 = Ar1[MT]; a1v2 = Ar1[2 * (size_t)MT]; a1v3 = Ar1[3 * (size_t)MT]; \
        bv0  = Br[0];  bv1  = Br[MT];  bv2  = Br[2 * (size_t)MT];  bv3  = Br[3 * (size_t)MT];  \
    } while (0)

#define PACK_STORE(base_w, v0, v1, v2, v3)                                           \
    do {                                                                             \
        uint32_t h0 = pack_bf16x2(v1, v0);                                           \
        uint32_t h1 = pack_bf16x2(v3, v2);                                           \
        uint32_t l0 = pack_bf16x2(v1 - __uint_as_float(h0 & 0xffff0000u),            \
                                  v0 - __uint_as_float(h0 << 16));                   \
        uint32_t l1 = pack_bf16x2(v3 - __uint_as_float(h1 & 0xffff0000u),            \
                                  v2 - __uint_as_float(h1 << 16));                   \
        *reinterpret_cast<uint2*>(&smemw[(base_w)])     = make_uint2(h0, h1);        \
        *reinterpret_cast<uint2*>(&smemw[(base_w) + 8]) = make_uint2(l0, l1);        \
    } while (0)

#define STORE_CHUNK(bufw)                                                            \
    do {                                                                             \
        PACK_STORE((bufw) + colA * 20 + 2 * kgA,       a0v0, a0v1, a0v2, a0v3);      \
        PACK_STORE((bufw) + colA * 20 + 2 * (kgA + 2), a1v0, a1v1, a1v2, a1v3);      \
        PACK_STORE((bufw) + 2560 + colB * 20 + 2 * kgB, bv0, bv1, bv2, bv3);         \
    } while (0)

    LOAD_CHUNK(0);
    STORE_CHUNK(0u);
    __syncthreads();

    for (int kb = 0; kb < 8; kb++) {
        if (kb < 7) LOAD_CHUNK(kb + 1);           // global prefetch (hidden by MMA)

        const uint32_t bw = (uint32_t)(kb & 1) * 3840u;
        uint32_t bh[2][4], bl[2][4];
        ldsm_x4(bh[0], sbase + (bw + boff0) * 4u);
        ldsm_x4(bl[0], sbase + (bw + boff0 + 8u) * 4u);
        ldsm_x4(bh[1], sbase + (bw + boff1) * 4u);
        ldsm_x4(bl[1], sbase + (bw + boff1 + 8u) * 4u);

#pragma unroll
        for (int mi = 0; mi < 2; mi++) {
            uint32_t ah[4], al[4];
            const uint32_t ao = (mi ? aoff1 : aoff0);
            ldsm_x4(ah, sbase + (bw + ao) * 4u);
            ldsm_x4(al, sbase + (bw + ao + 8u) * 4u);
#pragma unroll
            for (int j = 0; j < 4; j++) {
                const uint32_t* bfh = &bh[j >> 1][(j & 1) * 2];
                const uint32_t* bfl = &bl[j >> 1][(j & 1) * 2];
                mma_bf16(acc[mi][j], al, bfh);   // lo*hi
                mma_bf16(acc[mi][j], ah, bfl);   // hi*lo
                mma_bf16(acc[mi][j], ah, bfh);   // hi*hi
            }
        }

        if (kb < 7) STORE_CHUNK((uint32_t)((kb + 1) & 1) * 3840u);
        __syncthreads();
    }
#undef LOAD_CHUNK
#undef PACK_STORE
#undef STORE_CHUNK

    const float sc = 0.08838834764831845f;       // 1/sqrt(128)

    if constexpr (!FUSE) {
        // coarse: write scaled correlation to g_cc
        float* out = g_cc + (size_t)b * MT * MT;
        (void)outC; (void)outF;
#pragma unroll
        for (int mi = 0; mi < 2; mi++)
#pragma unroll
            for (int j = 0; j < 4; j++) {
                int r0 = m0 + wm0 + mi * 16 + gid;
                int cc = n0 + wn0 + j * 8 + 2 * tig;
                float2 v0 = make_float2(acc[mi][j][0] * sc, acc[mi][j][1] * sc);
                float2 v1 = make_float2(acc[mi][j][2] * sc, acc[mi][j][3] * sc);
                *reinterpret_cast<float2*>(&out[(size_t)r0 * MT + cc])       = v0;
                *reinterpret_cast<float2*>(&out[(size_t)(r0 + 8) * MT + cc]) = v1;
            }
    } else {
        // fine: c = 0.5*(rowinterp + corr), plus transposed write for c_flip
        float* S = reinterpret_cast<float*>(smemw);        // 128 x 65 (33.3 KB)
        float* Y = reinterpret_cast<float*>(smemw) + 8320; // 64 x 68  (17.4 KB)
        const size_t cb = (size_t)b * MT * MT;
        const int h0base = m0 >> 6;               // two h0 values: h0base, h0base+1

        // --- store corr into S (all 8 warps cover 128x64 disjointly) ---
#pragma unroll
        for (int mi = 0; mi < 2; mi++)
#pragma unroll
            for (int j = 0; j < 4; j++) {
                int r0  = wm0 + mi * 16 + gid;
                int col = wn0 + j * 8 + 2 * tig;
                S[r0 * 65 + col]           = acc[mi][j][0] * sc;
                S[r0 * 65 + col + 1]       = acc[mi][j][1] * sc;
                S[(r0 + 8) * 65 + col]     = acc[mi][j][2] * sc;
                S[(r0 + 8) * 65 + col + 1] = acc[mi][j][3] * sc;
            }

        // --- build Y: y-blend of g_i1 rows for 2 h0 values, 32 cx, 64 cols ---
#pragma unroll
        for (int t = 0; t < 4; t++) {
            int e     = tid + t * 256;            // 0..1023
            int h0loc = e >> 9;
            int cx    = (e >> 4) & 31;
            int c4    = e & 15;
            int y0, y1; float wy;
            lerp_weights(h0base + h0loc, y0, y1, wy);
            const float4* p0 = reinterpret_cast<const float4*>(
                g_i1 + ((size_t)b * 1024 + y0 * 32 + cx) * 4096 + n0) + c4;
            const float4* p1 = reinterpret_cast<const float4*>(
                g_i1 + ((size_t)b * 1024 + y1 * 32 + cx) * 4096 + n0) + c4;
            float4 a = *p0, bb = *p1;
            float4 v;
            v.x = a.x + wy * (bb.x - a.x);
            v.y = a.y + wy * (bb.y - a.y);
            v.z = a.z + wy * (bb.z - a.z);
            v.w = a.w + wy * (bb.w - a.w);
            *reinterpret_cast<float4*>(&Y[(h0loc * 32 + cx) * 68 + c4 * 4]) = v;
        }
        __syncthreads();

        // --- combine: x-blend + corr, write c, keep combined in S ---
#pragma unroll
        for (int q = 0; q < 8; q++) {
            int idx = tid + q * 256;              // float4 units over 128x64
            int r   = idx >> 4;
            int cf  = (idx & 15) << 2;
            int h0loc = r >> 6;
            int w0    = r & 63;
            int x0, x1; float wx;
            lerp_weights(w0, x0, x1, wx);
            float4 ya = *reinterpret_cast<const float4*>(&Y[(h0loc * 32 + x0) * 68 + cf]);
            float4 yb = *reinterpret_cast<const float4*>(&Y[(h0loc * 32 + x1) * 68 + cf]);
            float4 ip;
            ip.x = ya.x + wx * (yb.x - ya.x);
            ip.y = ya.y + wx * (yb.y - ya.y);
            ip.z = ya.z + wx * (yb.z - ya.z);
            ip.w = ya.w + wx * (yb.w - ya.w);
            size_t ga = cb + (size_t)(m0 + r) * MT + n0 + cf;
            float4 v;
            v.x = 0.5f * (ip.x + S[r * 65 + cf]);
            v.y = 0.5f * (ip.y + S[r * 65 + cf + 1]);
            v.z = 0.5f * (ip.z + S[r * 65 + cf + 2]);
            v.w = 0.5f * (ip.w + S[r * 65 + cf + 3]);
            *reinterpret_cast<float4*>(outC + ga) = v;
            S[r * 65 + cf]     = v.x;             // keep combined value for flip write
            S[r * 65 + cf + 1] = v.y;
            S[r * 65 + cf + 2] = v.z;
            S[r * 65 + cf + 3] = v.w;
        }
        __syncthreads();

        // --- transposed rows: c_flip[n][m0..m0+127] ---
#pragma unroll
        for (int jr = 0; jr < 8; jr++) {
            int n = warp * 8 + jr;
            size_t fb = cb + (size_t)(n0 + n) * MT + m0;
#pragma unroll
            for (int q = 0; q < 4; q++) {
                int m = lane + q * 32;            // bank = (m+n)%32 -> conflict-free
                outF[fb + m] = S[m * 65 + n];
            }
        }
    }
}

// ---------------------------------------------------------------------------
// trans_features_coarse: bilinear 32->64 (align_corners) per channel
// ---------------------------------------------------------------------------
__global__ __launch_bounds__(256)
void resize_coarse_kernel(const float* __restrict__ a, const float* __restrict__ bsrc,
                          float* __restrict__ out)
{
    __shared__ float s[1024];
    int blk = blockIdx.x;                        // 0..511
    int bb = blk >> 8, ii = (blk >> 7) & 1, ch = blk & 127;
    const float* in = (ii ? bsrc : a) + ((size_t)bb * 128 + ch) * 1024;
    float* o = out + (((size_t)bb * 2 + ii) * 128 + ch) * 4096;
    int tid = threadIdx.x;
#pragma unroll
    for (int q = 0; q < 4; q++) s[tid + q * 256] = in[tid + q * 256];
    __syncthreads();
#pragma unroll
    for (int q = 0; q < 16; q++) {
        int oi = tid + q * 256;
        int oy = oi >> 6, ox = oi & 63;
        int y0, y1, x0, x1; float wy, wx;
        lerp_weights(oy, y0, y1, wy);
        lerp_weights(ox, x0, x1, wx);
        float v = (1.0f - wy) * ((1.0f - wx) * s[y0 * 32 + x0] + wx * s[y0 * 32 + x1])
                +         wy  * ((1.0f - wx) * s[y1 * 32 + x0] + wx * s[y1 * 32 + x1]);
        o[oi] = v;
    }
}

// ---------------------------------------------------------------------------
// interp pass A: per (b,p0c) row, upsample (u,v) 32x32 -> 64x64
// ---------------------------------------------------------------------------
__global__ __launch_bounds__(256)
void interpA_kernel()
{
    __shared__ float s[1024];
    int blk = blockIdx.x;                        // 0..2047 = b*1024 + p0c
    const float* in = g_cc + (size_t)blk * 1024;
    float* o = g_i1 + (size_t)blk * 4096;
    int tid = threadIdx.x;
#pragma unroll
    for (int q = 0; q < 4; q++) s[tid + q * 256] = in[tid + q * 256];
    __syncthreads();
#pragma unroll
    for (int q = 0; q < 16; q++) {
        int oi = tid + q * 256;
        int oy = oi >> 6, ox = oi & 63;
        int y0, y1, x0, x1; float wy, wx;
        lerp_weights(oy, y0, y1, wy);
        lerp_weights(ox, x0, x1, wx);
        float v = (1.0f - wy) * ((1.0f - wx) * s[y0 * 32 + x0] + wx * s[y0 * 32 + x1])
                +         wy  * ((1.0f - wx) * s[y1 * 32 + x0] + wx * s[y1 * 32 + x1]);
        o[oi] = v;
    }
}

// ---------------------------------------------------------------------------
// soft-argmax: softmax(row/0.02) over 4096 source positions, marginal means.
// TWO rows per block (MLP 8 on the loads; reductions share barriers).
// L2-locality: iterate b=1 first, rows descending (GEMM-tail data still in L2).
// grid (2048, 2, 2): rows {t0, t0+1}, y = batch, z = c/c_flip select.
// ---------------------------------------------------------------------------
__global__ __launch_bounds__(256)
void softargmax_kernel(const float* __restrict__ c0, const float* __restrict__ c1,
                       float* __restrict__ fl0, float* __restrict__ fl1)
{
    const int t0 = 4094 - 2 * (int)blockIdx.x;   // descending row pairs
    const int bb = 1 - (int)blockIdx.y;          // batch 1 first
    const float* cmat = blockIdx.z ? c1 : c0;
    float* flow       = blockIdx.z ? fl1 : fl0;
    const float* row0 = cmat + ((size_t)bb * 4096 + t0) * 4096;
    const float* row1 = row0 + 4096;
    const int tid = threadIdx.x;
    const int warp = tid >> 5, lane = tid & 31;

    // issue all 8 float4 loads up front (MLP 8)
    float4 a0[4], a1[4];
    const float4* r40 = reinterpret_cast<const float4*>(row0) + tid * 4;
    const float4* r41 = reinterpret_cast<const float4*>(row1) + tid * 4;
#pragma unroll
    for (int q = 0; q < 4; q++) a0[q] = r40[q];
#pragma unroll
    for (int q = 0; q < 4; q++) a1[q] = r41[q];

    float v0[16], v1[16];
#pragma unroll
    for (int q = 0; q < 4; q++) {
        v0[q * 4] = a0[q].x; v0[q * 4 + 1] = a0[q].y; v0[q * 4 + 2] = a0[q].z; v0[q * 4 + 3] = a0[q].w;
        v1[q * 4] = a1[q].x; v1[q * 4 + 1] = a1[q].y; v1[q * 4 + 2] = a1[q].z; v1[q * 4 + 3] = a1[q].w;
    }

    float mx0 = v0[0], mx1 = v1[0];
#pragma unroll
    for (int e = 1; e < 16; e++) { mx0 = fmaxf(mx0, v0[e]); mx1 = fmaxf(mx1, v1[e]); }
#pragma unroll
    for (int o = 16; o; o >>= 1) {
        mx0 = fmaxf(mx0, __shfl_xor_sync(0xffffffffu, mx0, o));
        mx1 = fmaxf(mx1, __shfl_xor_sync(0xffffffffu, mx1, o));
    }

    __shared__ float smax[16];
    if (lane == 0) { smax[warp] = mx0; smax[8 + warp] = mx1; }
    __syncthreads();
    mx0 = smax[0]; mx1 = smax[8];
#pragma unroll
    for (int i = 1; i < 8; i++) { mx0 = fmaxf(mx0, smax[i]); mx1 = fmaxf(mx1, smax[8 + i]); }

    float Z0 = 0.0f, Sx0 = 0.0f, Sy0 = 0.0f;
    float Z1 = 0.0f, Sx1 = 0.0f, Sy1 = 0.0f;
    const int base = tid * 16;
#pragma unroll
    for (int e = 0; e < 16; e++) {
        int idx = base + e;
        float xn = (float)((idx & 63) * 2) / 63.0f - 1.0f;
        float yn = (float)((idx >> 6) * 2) / 63.0f - 1.0f;
        float d0 = (v0[e] - mx0) * 50.0f;         // /beta = *50
        if (d0 > -25.0f) {                        // skipped terms < 1.4e-11 * Z
            float ee = __expf(d0);
            Z0 += ee; Sx0 += ee * xn; Sy0 += ee * yn;
        }
        float d1 = (v1[e] - mx1) * 50.0f;
        if (d1 > -25.0f) {
            float ee = __expf(d1);
            Z1 += ee; Sx1 += ee * xn; Sy1 += ee * yn;
        }
    }
#pragma unroll
    for (int o = 16; o; o >>= 1) {
        Z0  += __shfl_xor_sync(0xffffffffu, Z0,  o);
        Sx0 += __shfl_xor_sync(0xffffffffu, Sx0, o);
        Sy0 += __shfl_xor_sync(0xffffffffu, Sy0, o);
        Z1  += __shfl_xor_sync(0xffffffffu, Z1,  o);
        Sx1 += __shfl_xor_sync(0xffffffffu, Sx1, o);
        Sy1 += __shfl_xor_sync(0xffffffffu, Sy1, o);
    }
    __shared__ float sz[16], sxs[16], sys[16];
    if (lane == 0) {
        sz[warp] = Z0; sxs[warp] = Sx0; sys[warp] = Sy0;
        sz[8 + warp] = Z1; sxs[8 + warp] = Sx1; sys[8 + warp] = Sy1;
    }
    __syncthreads();
    if (tid < 2) {
        const int t = t0 + tid;
        const int off = tid * 8;
        float z = 0.0f, X = 0.0f, Yv = 0.0f;
#pragma unroll
        for (int i = 0; i < 8; i++) { z += sz[off + i]; X += sxs[off + i]; Yv += sys[off + i]; }
        float gx = X / z, gy = Yv / z;
        float w = (float)(t & 63), h = (float)(t >> 6);
        flow[(size_t)bb * 2 * 4096 + t]        = (gx + 1.0f) * 31.5f - w;
        flow[(size_t)bb * 2 * 4096 + 4096 + t] = (gy + 1.0f) * 31.5f - h;
    }
}

// ---------------------------------------------------------------------------
// launch
// ---------------------------------------------------------------------------
extern "C" void kernel_launch(void* const* d_in, const int* in_sizes, int n_in,
                              void* d_out, int out_size)
{
    (void)in_sizes; (void)n_in; (void)out_size;
    const float* f0c = (const float*)d_in[0];
    const float* f1c = (const float*)d_in[1];
    const float* f0f = (const float*)d_in[2];
    const float* f1f = (const float*)d_in[3];
    float* out = (float*)d_out;

    cudaFuncSetAttribute(gemm_corr_kernel<4096, true>,
                         cudaFuncAttributeMaxDynamicSharedMemorySize, 50688);

    // trans_features = stack([feat0_f, feat1_f], axis=1)
    const size_t chunk = (size_t)128 * 4096;
    cudaMemcpyAsync(out + OFF_TF + 0 * chunk, f0f,         chunk * 4, cudaMemcpyDeviceToDevice, 0);
    cudaMemcpyAsync(out + OFF_TF + 1 * chunk, f1f,         chunk * 4, cudaMemcpyDeviceToDevice, 0);
    cudaMemcpyAsync(out + OFF_TF + 2 * chunk, f0f + chunk, chunk * 4, cudaMemcpyDeviceToDevice, 0);
    cudaMemcpyAsync(out + OFF_TF + 3 * chunk, f1f + chunk, chunk * 4, cudaMemcpyDeviceToDevice, 0);

    resize_coarse_kernel<<<512, 256>>>(f0c, f1c, out + OFF_TFC);

    gemm_corr_kernel<1024, false><<<dim3(16, 8, 2), 256, 30720>>>(f0c, f1c, nullptr, nullptr);
    interpA_kernel<<<2048, 256>>>();
    gemm_corr_kernel<4096, true><<<dim3(64, 32, 2), 256, 50688>>>(f0f, f1f, out + OFF_C, out + OFF_CF);

    softargmax_kernel<<<dim3(2048, 2, 2), 256>>>(out + OFF_C, out + OFF_CF,
                                                 out + OFF_FLOW, out + OFF_FLOWF);
}

// round 14
// speedup vs baseline: 1.2897x; 1.1563x over previous
#include <cuda_runtime.h>
#include <cstdint>

// ---------------------------------------------------------------------------
// Problem constants
//   feat0_c, feat1_c : [2,128,32,32] fp32
//   feat0_f, feat1_f : [2,128,64,64] fp32
// ---------------------------------------------------------------------------

static const size_t OFF_TF    = 0;
static const size_t OFF_TFC   = 2097152;
static const size_t OFF_C     = 4194304;
static const size_t OFF_CF    = 37748736;
static const size_t OFF_FLOW  = 71303168;
static const size_t OFF_FLOWF = 71319552;

// Scratch (device globals — no allocation allowed)
__device__ float g_cc[2 * 1024 * 1024];          // corr_c  [b][p0c][p1c]   8 MB
__device__ float g_i1[2 * 1024 * 4096];          // (u,v)-upsampled corr_c  33.5 MB (L2-resident)

// ---------------------------------------------------------------------------
// helpers
// ---------------------------------------------------------------------------
__device__ __forceinline__ uint32_t pack_bf16x2(float hi, float lo) {
    uint32_t r;
    asm("cvt.rn.bf16x2.f32 %0, %1, %2;" : "=r"(r) : "f"(hi), "f"(lo));
    return r;
}

__device__ __forceinline__ void mma_bf16(float* d, const uint32_t* a, const uint32_t* b) {
    asm volatile(
        "mma.sync.aligned.m16n8k16.row.col.f32.bf16.bf16.f32 "
        "{%0,%1,%2,%3}, {%4,%5,%6,%7}, {%8,%9}, {%0,%1,%2,%3};\n"
        : "+f"(d[0]), "+f"(d[1]), "+f"(d[2]), "+f"(d[3])
        : "r"(a[0]), "r"(a[1]), "r"(a[2]), "r"(a[3]), "r"(b[0]), "r"(b[1]));
}

__device__ __forceinline__ void ldsm_x4(uint32_t* r, uint32_t saddr) {
    asm volatile("ldmatrix.sync.aligned.m8n8.x4.shared.b16 {%0,%1,%2,%3}, [%4];"
                 : "=r"(r[0]), "=r"(r[1]), "=r"(r[2]), "=r"(r[3]) : "r"(saddr));
}

__device__ __forceinline__ void lerp_weights(int i, int& i0, int& i1, float& w) {
    float f = (float)(i * 31) / 63.0f;   // align_corners scale 31/63, exact at i=0,63
    i0 = (int)f;
    w  = f - (float)i0;
    i1 = min(i0 + 1, 31);
}

// ---------------------------------------------------------------------------
// Correlation GEMM (bf16x3, near-fp32 accuracy), 256 threads / 8 warps,
// 2 CTAs per SM. Block tile 128(m) x 64(n), warp tile 32x32, BK=16,
// mma.m16n8k16 + ldmatrix.x4, double-buffered smem.
// FUSE epilogue: c = 0.5*(rowinterp(g_i1) + corr), writes c + c_flip.
// ---------------------------------------------------------------------------
template <int MT, bool FUSE>
__global__ __launch_bounds__(256, 2)
void gemm_corr_kernel(const float* __restrict__ f0, const float* __restrict__ f1,
                      float* __restrict__ outC, float* __restrict__ outF)
{
    extern __shared__ uint32_t smemw[];

    const int b  = blockIdx.z;
    const int m0 = blockIdx.y * 128;
    const int n0 = blockIdx.x * 64;
    const float* A  = f0 + (size_t)b * 128 * MT;  // [K=128][MT]
    const float* Bg = f1 + (size_t)b * 128 * MT;

    const int tid  = threadIdx.x;
    const int warp = tid >> 5, lane = tid & 31;
    const int gid  = lane >> 2, tig = lane & 3;
    const int wm0  = (warp >> 1) * 32;           // 4 warp rows
    const int wn0  = (warp & 1) * 32;            // 2 warp cols

    float acc[2][4][4];
#pragma unroll
    for (int mi = 0; mi < 2; mi++)
#pragma unroll
        for (int j = 0; j < 4; j++)
#pragma unroll
            for (int r = 0; r < 4; r++) acc[mi][j][r] = 0.0f;

    // ---- producer mapping ----
    const int colA = tid & 127;
    const int kgA  = tid >> 7;                   // 0..1
    const int colB = tid & 63;
    const int kgB  = tid >> 6;                   // 0..3

    const uint32_t sbase = (uint32_t)__cvta_generic_to_shared(smemw);

    // ---- consumer ldmatrix row offsets (word units) ----
    const int Lm = lane & 7;
    const int mrowA = ((lane >> 3) & 1) * 8 + Lm;
    const int koffA = (lane >> 4) * 4;
    const uint32_t aoff0 = (uint32_t)((wm0 + mrowA) * 20 + koffA);
    const uint32_t aoff1 = (uint32_t)((wm0 + 16 + mrowA) * 20 + koffA);
    const int nrowB = Lm + ((lane >> 4) << 3);
    const int koffB = ((lane >> 3) & 1) * 4;
    const uint32_t boff0 = (uint32_t)(2560 + (wn0 + nrowB) * 20 + koffB);
    const uint32_t boff1 = (uint32_t)(2560 + (wn0 + 16 + nrowB) * 20 + koffB);

    float a0v0, a0v1, a0v2, a0v3;
    float a1v0, a1v1, a1v2, a1v3;
    float bv0, bv1, bv2, bv3;

#define LOAD_CHUNK(kb)                                                               \
    do {                                                                             \
        const float* Ar0 = A + (size_t)((kb) * 16 + kgA * 4) * MT + m0 + colA;       \
        const float* Ar1 = A + (size_t)((kb) * 16 + (kgA + 2) * 4) * MT + m0 + colA; \
        const float* Br  = Bg + (size_t)((kb) * 16 + kgB * 4) * MT + n0 + colB;      \
        a0v0 = Ar0[0]; a0v1 = Ar0[MT]; a0v2 = Ar0[2 * (size_t)MT]; a0v3 = Ar0[3 * (size_t)MT]; \
        a1v0 = Ar1[0]; a1v1 = Ar1[MT]; a1v2 = Ar1[2 * (size_t)MT]; a1v3 = Ar1[3 * (size_t)MT]; \
        bv0  = Br[0];  bv1  = Br[MT];  bv2  = Br[2 * (size_t)MT];  bv3  = Br[3 * (size_t)MT];  \
    } while (0)

#define PACK_STORE(base_w, v0, v1, v2, v3)                                           \
    do {                                                                             \
        uint32_t h0 = pack_bf16x2(v1, v0);                                           \
        uint32_t h1 = pack_bf16x2(v3, v2);                                           \
        uint32_t l0 = pack_bf16x2(v1 - __uint_as_float(h0 & 0xffff0000u),            \
                                  v0 - __uint_as_float(h0 << 16));                   \
        uint32_t l1 = pack_bf16x2(v3 - __uint_as_float(h1 & 0xffff0000u),            \
                                  v2 - __uint_as_float(h1 << 16));                   \
        *reinterpret_cast<uint2*>(&smemw[(base_w)])     = make_uint2(h0, h1);        \
        *reinterpret_cast<uint2*>(&smemw[(base_w) + 8]) = make_uint2(l0, l1);        \
    } while (0)

#define STORE_CHUNK(bufw)                                                            \
    do {                                                                             \
        PACK_STORE((bufw) + colA * 20 + 2 * kgA,       a0v0, a0v1, a0v2, a0v3);      \
        PACK_STORE((bufw) + colA * 20 + 2 * (kgA + 2), a1v0, a1v1, a1v2, a1v3);      \
        PACK_STORE((bufw) + 2560 + colB * 20 + 2 * kgB, bv0, bv1, bv2, bv3);         \
    } while (0)

    LOAD_CHUNK(0);
    STORE_CHUNK(0u);
    __syncthreads();

    for (int kb = 0; kb < 8; kb++) {
        if (kb < 7) LOAD_CHUNK(kb + 1);           // global prefetch (hidden by MMA)

        const uint32_t bw = (uint32_t)(kb & 1) * 3840u;
        uint32_t bh[2][4], bl[2][4];
        ldsm_x4(bh[0], sbase + (bw + boff0) * 4u);
        ldsm_x4(bl[0], sbase + (bw + boff0 + 8u) * 4u);
        ldsm_x4(bh[1], sbase + (bw + boff1) * 4u);
        ldsm_x4(bl[1], sbase + (bw + boff1 + 8u) * 4u);

#pragma unroll
        for (int mi = 0; mi < 2; mi++) {
            uint32_t ah[4], al[4];
            const uint32_t ao = (mi ? aoff1 : aoff0);
            ldsm_x4(ah, sbase + (bw + ao) * 4u);
            ldsm_x4(al, sbase + (bw + ao + 8u) * 4u);
#pragma unroll
            for (int j = 0; j < 4; j++) {
                const uint32_t* bfh = &bh[j >> 1][(j & 1) * 2];
                const uint32_t* bfl = &bl[j >> 1][(j & 1) * 2];
                mma_bf16(acc[mi][j], al, bfh);   // lo*hi
                mma_bf16(acc[mi][j], ah, bfl);   // hi*lo
                mma_bf16(acc[mi][j], ah, bfh);   // hi*hi
            }
        }

        if (kb < 7) STORE_CHUNK((uint32_t)((kb + 1) & 1) * 3840u);
        __syncthreads();
    }
#undef LOAD_CHUNK
#undef PACK_STORE
#undef STORE_CHUNK

    const float sc = 0.08838834764831845f;       // 1/sqrt(128)

    if constexpr (!FUSE) {
        // coarse: write scaled correlation to g_cc
        float* out = g_cc + (size_t)b * MT * MT;
        (void)outC; (void)outF;
#pragma unroll
        for (int mi = 0; mi < 2; mi++)
#pragma unroll
            for (int j = 0; j < 4; j++) {
                int r0 = m0 + wm0 + mi * 16 + gid;
                int cc = n0 + wn0 + j * 8 + 2 * tig;
                float2 v0 = make_float2(acc[mi][j][0] * sc, acc[mi][j][1] * sc);
                float2 v1 = make_float2(acc[mi][j][2] * sc, acc[mi][j][3] * sc);
                *reinterpret_cast<float2*>(&out[(size_t)r0 * MT + cc])       = v0;
                *reinterpret_cast<float2*>(&out[(size_t)(r0 + 8) * MT + cc]) = v1;
            }
    } else {
        // fine: c = 0.5*(rowinterp + corr), plus transposed write for c_flip
        float* S = reinterpret_cast<float*>(smemw);        // 128 x 65 (33.3 KB)
        float* Y = reinterpret_cast<float*>(smemw) + 8320; // 64 x 68  (17.4 KB)
        const size_t cb = (size_t)b * MT * MT;
        const int h0base = m0 >> 6;               // two h0 values: h0base, h0base+1

        // --- store corr into S (all 8 warps cover 128x64 disjointly) ---
#pragma unroll
        for (int mi = 0; mi < 2; mi++)
#pragma unroll
            for (int j = 0; j < 4; j++) {
                int r0  = wm0 + mi * 16 + gid;
                int col = wn0 + j * 8 + 2 * tig;
                S[r0 * 65 + col]           = acc[mi][j][0] * sc;
                S[r0 * 65 + col + 1]       = acc[mi][j][1] * sc;
                S[(r0 + 8) * 65 + col]     = acc[mi][j][2] * sc;
                S[(r0 + 8) * 65 + col + 1] = acc[mi][j][3] * sc;
            }

        // --- build Y: y-blend of g_i1 rows for 2 h0 values, 32 cx, 64 cols ---
#pragma unroll
        for (int t = 0; t < 4; t++) {
            int e     = tid + t * 256;            // 0..1023
            int h0loc = e >> 9;
            int cx    = (e >> 4) & 31;
            int c4    = e & 15;
            int y0, y1; float wy;
            lerp_weights(h0base + h0loc, y0, y1, wy);
            const float4* p0 = reinterpret_cast<const float4*>(
                g_i1 + ((size_t)b * 1024 + y0 * 32 + cx) * 4096 + n0) + c4;
            const float4* p1 = reinterpret_cast<const float4*>(
                g_i1 + ((size_t)b * 1024 + y1 * 32 + cx) * 4096 + n0) + c4;
            float4 a = *p0, bb = *p1;
            float4 v;
            v.x = a.x + wy * (bb.x - a.x);
            v.y = a.y + wy * (bb.y - a.y);
            v.z = a.z + wy * (bb.z - a.z);
            v.w = a.w + wy * (bb.w - a.w);
            *reinterpret_cast<float4*>(&Y[(h0loc * 32 + cx) * 68 + c4 * 4]) = v;
        }
        __syncthreads();

        // --- combine: x-blend + corr, write c, keep combined in S ---
#pragma unroll
        for (int q = 0; q < 8; q++) {
            int idx = tid + q * 256;              // float4 units over 128x64
            int r   = idx >> 4;
            int cf  = (idx & 15) << 2;
            int h0loc = r >> 6;
            int w0    = r & 63;
            int x0, x1; float wx;
            lerp_weights(w0, x0, x1, wx);
            float4 ya = *reinterpret_cast<const float4*>(&Y[(h0loc * 32 + x0) * 68 + cf]);
            float4 yb = *reinterpret_cast<const float4*>(&Y[(h0loc * 32 + x1) * 68 + cf]);
            float4 ip;
            ip.x = ya.x + wx * (yb.x - ya.x);
            ip.y = ya.y + wx * (yb.y - ya.y);
            ip.z = ya.z + wx * (yb.z - ya.z);
            ip.w = ya.w + wx * (yb.w - ya.w);
            size_t ga = cb + (size_t)(m0 + r) * MT + n0 + cf;
            float4 v;
            v.x = 0.5f * (ip.x + S[r * 65 + cf]);
            v.y = 0.5f * (ip.y + S[r * 65 + cf + 1]);
            v.z = 0.5f * (ip.z + S[r * 65 + cf + 2]);
            v.w = 0.5f * (ip.w + S[r * 65 + cf + 3]);
            *reinterpret_cast<float4*>(outC + ga) = v;
            S[r * 65 + cf]     = v.x;             // keep combined value for flip write
            S[r * 65 + cf + 1] = v.y;
            S[r * 65 + cf + 2] = v.z;
            S[r * 65 + cf + 3] = v.w;
        }
        __syncthreads();

        // --- transposed rows: c_flip[n][m0..m0+127] ---
#pragma unroll
        for (int jr = 0; jr < 8; jr++) {
            int n = warp * 8 + jr;
            size_t fb = cb + (size_t)(n0 + n) * MT + m0;
#pragma unroll
            for (int q = 0; q < 4; q++) {
                int m = lane + q * 32;            // bank = (m+n)%32 -> conflict-free
                outF[fb + m] = S[m * 65 + n];
            }
        }
    }
}

// ---------------------------------------------------------------------------
// trans_features copy: out[b][i][C*64*64] = stack([f0f, f1f], axis=1)
// single kernel replaces 4 memcpy graph nodes. 2M floats = 512K float4.
// ---------------------------------------------------------------------------
__global__ __launch_bounds__(256)
void tf_copy_kernel(const float* __restrict__ f0f, const float* __restrict__ f1f,
                    float* __restrict__ out)
{
    const size_t chunk4 = (size_t)128 * 1024;    // float4 per (b,i)
    size_t idx = (size_t)blockIdx.x * 256 + threadIdx.x;
#pragma unroll
    for (int q = 0; q < 4; q++) {
        size_t e  = idx + (size_t)q * 131072;    // 512 blocks x 256 thr = 131072/iter
        size_t bi = e / chunk4;                  // 0..3 = (b<<1)|i
        size_t off = e - bi * chunk4;
        const float4* src = reinterpret_cast<const float4*>((bi & 1) ? f1f : f0f)
                          + (bi >> 1) * chunk4 + off;
        reinterpret_cast<float4*>(out)[e] = *src;
    }
}

// ---------------------------------------------------------------------------
// trans_features_coarse: bilinear 32->64 (align_corners) per channel
// ---------------------------------------------------------------------------
__global__ __launch_bounds__(256)
void resize_coarse_kernel(const float* __restrict__ a, const float* __restrict__ bsrc,
                          float* __restrict__ out)
{
    __shared__ float s[1024];
    int blk = blockIdx.x;                        // 0..511
    int bb = blk >> 8, ii = (blk >> 7) & 1, ch = blk & 127;
    const float* in = (ii ? bsrc : a) + ((size_t)bb * 128 + ch) * 1024;
    float* o = out + (((size_t)bb * 2 + ii) * 128 + ch) * 4096;
    int tid = threadIdx.x;
#pragma unroll
    for (int q = 0; q < 4; q++) s[tid + q * 256] = in[tid + q * 256];
    __syncthreads();
#pragma unroll
    for (int q = 0; q < 16; q++) {
        int oi = tid + q * 256;
        int oy = oi >> 6, ox = oi & 63;
        int y0, y1, x0, x1; float wy, wx;
        lerp_weights(oy, y0, y1, wy);
        lerp_weights(ox, x0, x1, wx);
        float v = (1.0f - wy) * ((1.0f - wx) * s[y0 * 32 + x0] + wx * s[y0 * 32 + x1])
                +         wy  * ((1.0f - wx) * s[y1 * 32 + x0] + wx * s[y1 * 32 + x1]);
        o[oi] = v;
    }
}

// ---------------------------------------------------------------------------
// interp pass A: per (b,p0c) row, upsample (u,v) 32x32 -> 64x64
// ---------------------------------------------------------------------------
__global__ __launch_bounds__(256)
void interpA_kernel()
{
    __shared__ float s[1024];
    int blk = blockIdx.x;                        // 0..2047 = b*1024 + p0c
    const float* in = g_cc + (size_t)blk * 1024;
    float* o = g_i1 + (size_t)blk * 4096;
    int tid = threadIdx.x;
#pragma unroll
    for (int q = 0; q < 4; q++) s[tid + q * 256] = in[tid + q * 256];
    __syncthreads();
#pragma unroll
    for (int q = 0; q < 16; q++) {
        int oi = tid + q * 256;
        int oy = oi >> 6, ox = oi & 63;
        int y0, y1, x0, x1; float wy, wx;
        lerp_weights(oy, y0, y1, wy);
        lerp_weights(ox, x0, x1, wx);
        float v = (1.0f - wy) * ((1.0f - wx) * s[y0 * 32 + x0] + wx * s[y0 * 32 + x1])
                +         wy  * ((1.0f - wx) * s[y1 * 32 + x0] + wx * s[y1 * 32 + x1]);
        o[oi] = v;
    }
}

// ---------------------------------------------------------------------------
// soft-argmax: softmax(row/0.02) over 4096 source positions, marginal means.
// One block per (target pixel, batch); z selects (c -> flow) / (c_flip -> flow_flip).
// L2-locality: iterate b=1 first, rows descending (GEMM-tail data still in L2).
// ---------------------------------------------------------------------------
__global__ __launch_bounds__(256)
void softargmax_kernel(const float* __restrict__ c0, const float* __restrict__ c1,
                       float* __restrict__ fl0, float* __restrict__ fl1)
{
    const int t  = 4095 - blockIdx.x;            // descending rows (GEMM tail first)
    const int bb = 1 - blockIdx.y;               // batch 1 first (still L2-resident)
    const float* cmat = blockIdx.z ? c1 : c0;
    float* flow       = blockIdx.z ? fl1 : fl0;
    const float* row = cmat + ((size_t)bb * 4096 + t) * 4096;
    const int tid = threadIdx.x;
    const int warp = tid >> 5, lane = tid & 31;

    float v[16];
    const float4* r4 = reinterpret_cast<const float4*>(row) + tid * 4;
#pragma unroll
    for (int q = 0; q < 4; q++) {
        float4 x = r4[q];
        v[q * 4] = x.x; v[q * 4 + 1] = x.y; v[q * 4 + 2] = x.z; v[q * 4 + 3] = x.w;
    }

    float mx = v[0];
#pragma unroll
    for (int e = 1; e < 16; e++) mx = fmaxf(mx, v[e]);
#pragma unroll
    for (int o = 16; o; o >>= 1) mx = fmaxf(mx, __shfl_xor_sync(0xffffffffu, mx, o));

    __shared__ float smax[8];
    if (lane == 0) smax[warp] = mx;
    __syncthreads();
    mx = smax[0];
#pragma unroll
    for (int i = 1; i < 8; i++) mx = fmaxf(mx, smax[i]);

    float Z = 0.0f, Sx = 0.0f, Sy = 0.0f;
    const int base = tid * 16;
#pragma unroll
    for (int e = 0; e < 16; e++) {
        float tt = (v[e] - mx) * 50.0f;           // /beta = *50
        if (tt > -25.0f) {                        // skipped terms < 1.4e-11 * Z
            float ee = __expf(tt);
            int idx = base + e;
            float xn = (float)((idx & 63) * 2) / 63.0f - 1.0f;
            float yn = (float)((idx >> 6) * 2) / 63.0f - 1.0f;
            Z += ee; Sx += ee * xn; Sy += ee * yn;
        }
    }
#pragma unroll
    for (int o = 16; o; o >>= 1) {
        Z  += __shfl_xor_sync(0xffffffffu, Z,  o);
        Sx += __shfl_xor_sync(0xffffffffu, Sx, o);
        Sy += __shfl_xor_sync(0xffffffffu, Sy, o);
    }
    __shared__ float sz[8], sxs[8], sys[8];
    if (lane == 0) { sz[warp] = Z; sxs[warp] = Sx; sys[warp] = Sy; }
    __syncthreads();
    if (tid == 0) {
        float z = 0.0f, X = 0.0f, Yv = 0.0f;
#pragma unroll
        for (int i = 0; i < 8; i++) { z += sz[i]; X += sxs[i]; Yv += sys[i]; }
        float gx = X / z, gy = Yv / z;
        float w = (float)(t & 63), h = (float)(t >> 6);
        flow[(size_t)bb * 2 * 4096 + t]        = (gx + 1.0f) * 31.5f - w;
        flow[(size_t)bb * 2 * 4096 + 4096 + t] = (gy + 1.0f) * 31.5f - h;
    }
}

// ---------------------------------------------------------------------------
// launch
// ---------------------------------------------------------------------------
extern "C" void kernel_launch(void* const* d_in, const int* in_sizes, int n_in,
                              void* d_out, int out_size)
{
    (void)in_sizes; (void)n_in; (void)out_size;
    const float* f0c = (const float*)d_in[0];
    const float* f1c = (const float*)d_in[1];
    const float* f0f = (const float*)d_in[2];
    const float* f1f = (const float*)d_in[3];
    float* out = (float*)d_out;

    cudaFuncSetAttribute(gemm_corr_kernel<4096, true>,
                         cudaFuncAttributeMaxDynamicSharedMemorySize, 50688);

    // trans_features = stack([feat0_f, feat1_f], axis=1) — single copy kernel
    tf_copy_kernel<<<512, 256>>>(f0f, f1f, out + OFF_TF);

    resize_coarse_kernel<<<512, 256>>>(f0c, f1c, out + OFF_TFC);

    gemm_corr_kernel<1024, false><<<dim3(16, 8, 2), 256, 30720>>>(f0c, f1c, nullptr, nullptr);
    interpA_kernel<<<2048, 256>>>();
    gemm_corr_kernel<4096, true><<<dim3(64, 32, 2), 256, 50688>>>(f0f, f1f, out + OFF_C, out + OFF_CF);

    softargmax_kernel<<<dim3(4096, 2, 2), 256>>>(out + OFF_C, out + OFF_CF,
                                                 out + OFF_FLOW, out + OFF_FLOWF);
}

// round 15
// speedup vs baseline: 1.3111x; 1.0166x over previous
#include <cuda_runtime.h>
#include <cstdint>

// ---------------------------------------------------------------------------
// Problem constants
//   feat0_c, feat1_c : [2,128,32,32] fp32
//   feat0_f, feat1_f : [2,128,64,64] fp32
// ---------------------------------------------------------------------------

static const size_t OFF_TF    = 0;
static const size_t OFF_TFC   = 2097152;
static const size_t OFF_C     = 4194304;
static const size_t OFF_CF    = 37748736;
static const size_t OFF_FLOW  = 71303168;
static const size_t OFF_FLOWF = 71319552;

// Scratch (device globals — no allocation allowed)
__device__ float g_cc[2 * 1024 * 1024];          // corr_c  [b][p0c][p1c]   8 MB
__device__ float g_i1[2 * 1024 * 4096];          // (u,v)-upsampled corr_c  33.5 MB (L2-resident)

// ---------------------------------------------------------------------------
// helpers
// ---------------------------------------------------------------------------
__device__ __forceinline__ uint32_t pack_bf16x2(float hi, float lo) {
    uint32_t r;
    asm("cvt.rn.bf16x2.f32 %0, %1, %2;" : "=r"(r) : "f"(hi), "f"(lo));
    return r;
}

__device__ __forceinline__ void mma_bf16(float* d, const uint32_t* a, const uint32_t* b) {
    asm volatile(
        "mma.sync.aligned.m16n8k16.row.col.f32.bf16.bf16.f32 "
        "{%0,%1,%2,%3}, {%4,%5,%6,%7}, {%8,%9}, {%0,%1,%2,%3};\n"
        : "+f"(d[0]), "+f"(d[1]), "+f"(d[2]), "+f"(d[3])
        : "r"(a[0]), "r"(a[1]), "r"(a[2]), "r"(a[3]), "r"(b[0]), "r"(b[1]));
}

__device__ __forceinline__ void ldsm_x4(uint32_t* r, uint32_t saddr) {
    asm volatile("ldmatrix.sync.aligned.m8n8.x4.shared.b16 {%0,%1,%2,%3}, [%4];"
                 : "=r"(r[0]), "=r"(r[1]), "=r"(r[2]), "=r"(r[3]) : "r"(saddr));
}

__device__ __forceinline__ void lerp_weights(int i, int& i0, int& i1, float& w) {
    float f = (float)(i * 31) / 63.0f;   // align_corners scale 31/63, exact at i=0,63
    i0 = (int)f;
    w  = f - (float)i0;
    i1 = min(i0 + 1, 31);
}

// ---------------------------------------------------------------------------
// Correlation GEMM (bf16x3, near-fp32 accuracy), 256 threads / 8 warps,
// 2 CTAs per SM. Block tile 128(m) x 64(n), warp tile 32x32, BK=16,
// mma.m16n8k16 + ldmatrix.x4, double-buffered smem.
// FUSE epilogue: c = 0.5*(rowinterp(g_i1) + corr), writes c + c_flip.
// ---------------------------------------------------------------------------
template <int MT, bool FUSE>
__global__ __launch_bounds__(256, 2)
void gemm_corr_kernel(const float* __restrict__ f0, const float* __restrict__ f1,
                      float* __restrict__ outC, float* __restrict__ outF)
{
    extern __shared__ uint32_t smemw[];

    const int b  = blockIdx.z;
    const int m0 = blockIdx.y * 128;
    const int n0 = blockIdx.x * 64;
    const float* A  = f0 + (size_t)b * 128 * MT;  // [K=128][MT]
    const float* Bg = f1 + (size_t)b * 128 * MT;

    const int tid  = threadIdx.x;
    const int warp = tid >> 5, lane = tid & 31;
    const int gid  = lane >> 2, tig = lane & 3;
    const int wm0  = (warp >> 1) * 32;           // 4 warp rows
    const int wn0  = (warp & 1) * 32;            // 2 warp cols

    float acc[2][4][4];
#pragma unroll
    for (int mi = 0; mi < 2; mi++)
#pragma unroll
        for (int j = 0; j < 4; j++)
#pragma unroll
            for (int r = 0; r < 4; r++) acc[mi][j][r] = 0.0f;

    // ---- producer mapping ----
    const int colA = tid & 127;
    const int kgA  = tid >> 7;                   // 0..1
    const int colB = tid & 63;
    const int kgB  = tid >> 6;                   // 0..3

    const uint32_t sbase = (uint32_t)__cvta_generic_to_shared(smemw);

    // ---- consumer ldmatrix row offsets (word units) ----
    const int Lm = lane & 7;
    const int mrowA = ((lane >> 3) & 1) * 8 + Lm;
    const int koffA = (lane >> 4) * 4;
    const uint32_t aoff0 = (uint32_t)((wm0 + mrowA) * 20 + koffA);
    const uint32_t aoff1 = (uint32_t)((wm0 + 16 + mrowA) * 20 + koffA);
    const int nrowB = Lm + ((lane >> 4) << 3);
    const int koffB = ((lane >> 3) & 1) * 4;
    const uint32_t boff0 = (uint32_t)(2560 + (wn0 + nrowB) * 20 + koffB);
    const uint32_t boff1 = (uint32_t)(2560 + (wn0 + 16 + nrowB) * 20 + koffB);

    float a0v0, a0v1, a0v2, a0v3;
    float a1v0, a1v1, a1v2, a1v3;
    float bv0, bv1, bv2, bv3;

#define LOAD_CHUNK(kb)                                                               \
    do {                                                                             \
        const float* Ar0 = A + (size_t)((kb) * 16 + kgA * 4) * MT + m0 + colA;       \
        const float* Ar1 = A + (size_t)((kb) * 16 + (kgA + 2) * 4) * MT + m0 + colA; \
        const float* Br  = Bg + (size_t)((kb) * 16 + kgB * 4) * MT + n0 + colB;      \
        a0v0 = Ar0[0]; a0v1 = Ar0[MT]; a0v2 = Ar0[2 * (size_t)MT]; a0v3 = Ar0[3 * (size_t)MT]; \
        a1v0 = Ar1[0]; a1v1 = Ar1[MT]; a1v2 = Ar1[2 * (size_t)MT]; a1v3 = Ar1[3 * (size_t)MT]; \
        bv0  = Br[0];  bv1  = Br[MT];  bv2  = Br[2 * (size_t)MT];  bv3  = Br[3 * (size_t)MT];  \
    } while (0)

#define PACK_STORE(base_w, v0, v1, v2, v3)                                           \
    do {                                                                             \
        uint32_t h0 = pack_bf16x2(v1, v0);                                           \
        uint32_t h1 = pack_bf16x2(v3, v2);                                           \
        uint32_t l0 = pack_bf16x2(v1 - __uint_as_float(h0 & 0xffff0000u),            \
                                  v0 - __uint_as_float(h0 << 16));                   \
        uint32_t l1 = pack_bf16x2(v3 - __uint_as_float(h1 & 0xffff0000u),            \
                                  v2 - __uint_as_float(h1 << 16));                   \
        *reinterpret_cast<uint2*>(&smemw[(base_w)])     = make_uint2(h0, h1);        \
        *reinterpret_cast<uint2*>(&smemw[(base_w) + 8]) = make_uint2(l0, l1);        \
    } while (0)

#define STORE_CHUNK(bufw)                                                            \
    do {                                                                             \
        PACK_STORE((bufw) + colA * 20 + 2 * kgA,       a0v0, a0v1, a0v2, a0v3);      \
        PACK_STORE((bufw) + colA * 20 + 2 * (kgA + 2), a1v0, a1v1, a1v2, a1v3);      \
        PACK_STORE((bufw) + 2560 + colB * 20 + 2 * kgB, bv0, bv1, bv2, bv3);         \
    } while (0)

    LOAD_CHUNK(0);
    STORE_CHUNK(0u);
    __syncthreads();

    for (int kb = 0; kb < 8; kb++) {
        if (kb < 7) LOAD_CHUNK(kb + 1);           // global prefetch (hidden by MMA)

        const uint32_t bw = (uint32_t)(kb & 1) * 3840u;
        uint32_t bh[2][4], bl[2][4];
        ldsm_x4(bh[0], sbase + (bw + boff0) * 4u);
        ldsm_x4(bl[0], sbase + (bw + boff0 + 8u) * 4u);
        ldsm_x4(bh[1], sbase + (bw + boff1) * 4u);
        ldsm_x4(bl[1], sbase + (bw + boff1 + 8u) * 4u);

#pragma unroll
        for (int mi = 0; mi < 2; mi++) {
            uint32_t ah[4], al[4];
            const uint32_t ao = (mi ? aoff1 : aoff0);
            ldsm_x4(ah, sbase + (bw + ao) * 4u);
            ldsm_x4(al, sbase + (bw + ao + 8u) * 4u);
#pragma unroll
            for (int j = 0; j < 4; j++) {
                const uint32_t* bfh = &bh[j >> 1][(j & 1) * 2];
                const uint32_t* bfl = &bl[j >> 1][(j & 1) * 2];
                mma_bf16(acc[mi][j], al, bfh);   // lo*hi
                mma_bf16(acc[mi][j], ah, bfl);   // hi*lo
                mma_bf16(acc[mi][j], ah, bfh);   // hi*hi
            }
        }

        if (kb < 7) STORE_CHUNK((uint32_t)((kb + 1) & 1) * 3840u);
        __syncthreads();
    }
#undef LOAD_CHUNK
#undef PACK_STORE
#undef STORE_CHUNK

    const float sc = 0.08838834764831845f;       // 1/sqrt(128)

    if constexpr (!FUSE) {
        // coarse: write scaled correlation to g_cc
        float* out = g_cc + (size_t)b * MT * MT;
        (void)outC; (void)outF;
#pragma unroll
        for (int mi = 0; mi < 2; mi++)
#pragma unroll
            for (int j = 0; j < 4; j++) {
                int r0 = m0 + wm0 + mi * 16 + gid;
                int cc = n0 + wn0 + j * 8 + 2 * tig;
                float2 v0 = make_float2(acc[mi][j][0] * sc, acc[mi][j][1] * sc);
                float2 v1 = make_float2(acc[mi][j][2] * sc, acc[mi][j][3] * sc);
                *reinterpret_cast<float2*>(&out[(size_t)r0 * MT + cc])       = v0;
                *reinterpret_cast<float2*>(&out[(size_t)(r0 + 8) * MT + cc]) = v1;
            }
    } else {
        // fine: c = 0.5*(rowinterp + corr), plus transposed write for c_flip
        float* S = reinterpret_cast<float*>(smemw);        // 128 x 65 (33.3 KB)
        float* Y = reinterpret_cast<float*>(smemw) + 8320; // 64 x 68  (17.4 KB)
        const size_t cb = (size_t)b * MT * MT;
        const int h0base = m0 >> 6;               // two h0 values: h0base, h0base+1

        // --- store corr into S (all 8 warps cover 128x64 disjointly) ---
#pragma unroll
        for (int mi = 0; mi < 2; mi++)
#pragma unroll
            for (int j = 0; j < 4; j++) {
                int r0  = wm0 + mi * 16 + gid;
                int col = wn0 + j * 8 + 2 * tig;
                S[r0 * 65 + col]           = acc[mi][j][0] * sc;
                S[r0 * 65 + col + 1]       = acc[mi][j][1] * sc;
                S[(r0 + 8) * 65 + col]     = acc[mi][j][2] * sc;
                S[(r0 + 8) * 65 + col + 1] = acc[mi][j][3] * sc;
            }

        // --- build Y: y-blend of g_i1 rows for 2 h0 values, 32 cx, 64 cols ---
#pragma unroll
        for (int t = 0; t < 4; t++) {
            int e     = tid + t * 256;            // 0..1023
            int h0loc = e >> 9;
            int cx    = (e >> 4) & 31;
            int c4    = e & 15;
            int y0, y1; float wy;
            lerp_weights(h0base + h0loc, y0, y1, wy);
            const float4* p0 = reinterpret_cast<const float4*>(
                g_i1 + ((size_t)b * 1024 + y0 * 32 + cx) * 4096 + n0) + c4;
            const float4* p1 = reinterpret_cast<const float4*>(
                g_i1 + ((size_t)b * 1024 + y1 * 32 + cx) * 4096 + n0) + c4;
            float4 a = *p0, bb = *p1;
            float4 v;
            v.x = a.x + wy * (bb.x - a.x);
            v.y = a.y + wy * (bb.y - a.y);
            v.z = a.z + wy * (bb.z - a.z);
            v.w = a.w + wy * (bb.w - a.w);
            *reinterpret_cast<float4*>(&Y[(h0loc * 32 + cx) * 68 + c4 * 4]) = v;
        }
        __syncthreads();

        // --- combine: x-blend + corr, write c, keep combined in S ---
#pragma unroll
        for (int q = 0; q < 8; q++) {
            int idx = tid + q * 256;              // float4 units over 128x64
            int r   = idx >> 4;
            int cf  = (idx & 15) << 2;
            int h0loc = r >> 6;
            int w0    = r & 63;
            int x0, x1; float wx;
            lerp_weights(w0, x0, x1, wx);
            float4 ya = *reinterpret_cast<const float4*>(&Y[(h0loc * 32 + x0) * 68 + cf]);
            float4 yb = *reinterpret_cast<const float4*>(&Y[(h0loc * 32 + x1) * 68 + cf]);
            float4 ip;
            ip.x = ya.x + wx * (yb.x - ya.x);
            ip.y = ya.y + wx * (yb.y - ya.y);
            ip.z = ya.z + wx * (yb.z - ya.z);
            ip.w = ya.w + wx * (yb.w - ya.w);
            size_t ga = cb + (size_t)(m0 + r) * MT + n0 + cf;
            float4 v;
            v.x = 0.5f * (ip.x + S[r * 65 + cf]);
            v.y = 0.5f * (ip.y + S[r * 65 + cf + 1]);
            v.z = 0.5f * (ip.z + S[r * 65 + cf + 2]);
            v.w = 0.5f * (ip.w + S[r * 65 + cf + 3]);
            *reinterpret_cast<float4*>(outC + ga) = v;
            S[r * 65 + cf]     = v.x;             // keep combined value for flip write
            S[r * 65 + cf + 1] = v.y;
            S[r * 65 + cf + 2] = v.z;
            S[r * 65 + cf + 3] = v.w;
        }
        __syncthreads();

        // --- transposed rows: c_flip[n][m0..m0+127] ---
#pragma unroll
        for (int jr = 0; jr < 8; jr++) {
            int n = warp * 8 + jr;
            size_t fb = cb + (size_t)(n0 + n) * MT + m0;
#pragma unroll
            for (int q = 0; q < 4; q++) {
                int m = lane + q * 32;            // bank = (m+n)%32 -> conflict-free
                outF[fb + m] = S[m * 65 + n];
            }
        }
    }
}

// ---------------------------------------------------------------------------
// trans_features copy: out[b][i][C*64*64] = stack([f0f, f1f], axis=1)
// single kernel replaces 4 memcpy graph nodes. 2M floats = 512K float4.
// ---------------------------------------------------------------------------
__global__ __launch_bounds__(256)
void tf_copy_kernel(const float* __restrict__ f0f, const float* __restrict__ f1f,
                    float* __restrict__ out)
{
    const size_t chunk4 = (size_t)128 * 1024;    // float4 per (b,i)
    size_t idx = (size_t)blockIdx.x * 256 + threadIdx.x;
#pragma unroll
    for (int q = 0; q < 4; q++) {
        size_t e  = idx + (size_t)q * 131072;    // 512 blocks x 256 thr = 131072/iter
        size_t bi = e / chunk4;                  // 0..3 = (b<<1)|i
        size_t off = e - bi * chunk4;
        const float4* src = reinterpret_cast<const float4*>((bi & 1) ? f1f : f0f)
                          + (bi >> 1) * chunk4 + off;
        reinterpret_cast<float4*>(out)[e] = *src;
    }
}

// ---------------------------------------------------------------------------
// trans_features_coarse: bilinear 32->64 (align_corners) per channel.
// Weight/index tables hoisted into smem (ox fixed per thread, oy warp-uniform).
// Blend arithmetic identical to original -> bit-identical output.
// ---------------------------------------------------------------------------
__global__ __launch_bounds__(256)
void resize_coarse_kernel(const float* __restrict__ a, const float* __restrict__ bsrc,
                          float* __restrict__ out)
{
    __shared__ float s[1024];
    __shared__ float wT[64];
    __shared__ int   i0T[64], i1T[64];
    int blk = blockIdx.x;                        // 0..511
    int bb = blk >> 8, ii = (blk >> 7) & 1, ch = blk & 127;
    const float* in = (ii ? bsrc : a) + ((size_t)bb * 128 + ch) * 1024;
    float* o = out + (((size_t)bb * 2 + ii) * 128 + ch) * 4096;
    int tid = threadIdx.x;
#pragma unroll
    for (int q = 0; q < 4; q++) s[tid + q * 256] = in[tid + q * 256];
    if (tid < 64) {
        int i0, i1; float w;
        lerp_weights(tid, i0, i1, w);
        wT[tid] = w; i0T[tid] = i0; i1T[tid] = i1;
    }
    __syncthreads();
    const int   ox = tid & 63;
    const float wx = wT[ox];
    const int   x0 = i0T[ox], x1 = i1T[ox];
    const int   tidhi = tid >> 6;
#pragma unroll
    for (int q = 0; q < 16; q++) {
        int oy = tidhi + q * 4;
        float wy = wT[oy];
        int r0 = i0T[oy] * 32, r1 = i1T[oy] * 32;
        float v = (1.0f - wy) * ((1.0f - wx) * s[r0 + x0] + wx * s[r0 + x1])
                +         wy  * ((1.0f - wx) * s[r1 + x0] + wx * s[r1 + x1]);
        o[oy * 64 + ox] = v;
    }
}

// ---------------------------------------------------------------------------
// interp pass A: per (b,p0c) row, upsample (u,v) 32x32 -> 64x64.
// Same table-hoisted structure as resize_coarse (was ALU-bound at issue=79%).
// ---------------------------------------------------------------------------
__global__ __launch_bounds__(256)
void interpA_kernel()
{
    __shared__ float s[1024];
    __shared__ float wT[64];
    __shared__ int   i0T[64], i1T[64];
    int blk = blockIdx.x;                        // 0..2047 = b*1024 + p0c
    const float* in = g_cc + (size_t)blk * 1024;
    float* o = g_i1 + (size_t)blk * 4096;
    int tid = threadIdx.x;
#pragma unroll
    for (int q = 0; q < 4; q++) s[tid + q * 256] = in[tid + q * 256];
    if (tid < 64) {
        int i0, i1; float w;
        lerp_weights(tid, i0, i1, w);
        wT[tid] = w; i0T[tid] = i0; i1T[tid] = i1;
    }
    __syncthreads();
    const int   ox = tid & 63;
    const float wx = wT[ox];
    const int   x0 = i0T[ox], x1 = i1T[ox];
    const int   tidhi = tid >> 6;
#pragma unroll
    for (int q = 0; q < 16; q++) {
        int oy = tidhi + q * 4;
        float wy = wT[oy];
        int r0 = i0T[oy] * 32, r1 = i1T[oy] * 32;
        float v = (1.0f - wy) * ((1.0f - wx) * s[r0 + x0] + wx * s[r0 + x1])
                +         wy  * ((1.0f - wx) * s[r1 + x0] + wx * s[r1 + x1]);
        o[oy * 64 + ox] = v;
    }
}

// ---------------------------------------------------------------------------
// soft-argmax: softmax(row/0.02) over 4096 source positions, marginal means.
// One block per (target pixel, batch); z selects (c -> flow) / (c_flip -> flow_flip).
// L2-locality: iterate b=1 first, rows descending (GEMM-tail data still in L2).
// ---------------------------------------------------------------------------
__global__ __launch_bounds__(256)
void softargmax_kernel(const float* __restrict__ c0, const float* __restrict__ c1,
                       float* __restrict__ fl0, float* __restrict__ fl1)
{
    const int t  = 4095 - blockIdx.x;            // descending rows (GEMM tail first)
    const int bb = 1 - blockIdx.y;               // batch 1 first (still L2-resident)
    const float* cmat = blockIdx.z ? c1 : c0;
    float* flow       = blockIdx.z ? fl1 : fl0;
    const float* row = cmat + ((size_t)bb * 4096 + t) * 4096;
    const int tid = threadIdx.x;
    const int warp = tid >> 5, lane = tid & 31;

    float v[16];
    const float4* r4 = reinterpret_cast<const float4*>(row) + tid * 4;
#pragma unroll
    for (int q = 0; q < 4; q++) {
        float4 x = r4[q];
        v[q * 4] = x.x; v[q * 4 + 1] = x.y; v[q * 4 + 2] = x.z; v[q * 4 + 3] = x.w;
    }

    float mx = v[0];
#pragma unroll
    for (int e = 1; e < 16; e++) mx = fmaxf(mx, v[e]);
#pragma unroll
    for (int o = 16; o; o >>= 1) mx = fmaxf(mx, __shfl_xor_sync(0xffffffffu, mx, o));

    __shared__ float smax[8];
    if (lane == 0) smax[warp] = mx;
    __syncthreads();
    mx = smax[0];
#pragma unroll
    for (int i = 1; i < 8; i++) mx = fmaxf(mx, smax[i]);

    float Z = 0.0f, Sx = 0.0f, Sy = 0.0f;
    const int base = tid * 16;
#pragma unroll
    for (int e = 0; e < 16; e++) {
        float tt = (v[e] - mx) * 50.0f;           // /beta = *50
        if (tt > -25.0f) {                        // skipped terms < 1.4e-11 * Z
            float ee = __expf(tt);
            int idx = base + e;
            float xn = (float)((idx & 63) * 2) / 63.0f - 1.0f;
            float yn = (float)((idx >> 6) * 2) / 63.0f - 1.0f;
            Z += ee; Sx += ee * xn; Sy += ee * yn;
        }
    }
#pragma unroll
    for (int o = 16; o; o >>= 1) {
        Z  += __shfl_xor_sync(0xffffffffu, Z,  o);
        Sx += __shfl_xor_sync(0xffffffffu, Sx, o);
        Sy += __shfl_xor_sync(0xffffffffu, Sy, o);
    }
    __shared__ float sz[8], sxs[8], sys[8];
    if (lane == 0) { sz[warp] = Z; sxs[warp] = Sx; sys[warp] = Sy; }
    __syncthreads();
    if (tid == 0) {
        float z = 0.0f, X = 0.0f, Yv = 0.0f;
#pragma unroll
        for (int i = 0; i < 8; i++) { z += sz[i]; X += sxs[i]; Yv += sys[i]; }
        float gx = X / z, gy = Yv / z;
        float w = (float)(t & 63), h = (float)(t >> 6);
        flow[(size_t)bb * 2 * 4096 + t]        = (gx + 1.0f) * 31.5f - w;
        flow[(size_t)bb * 2 * 4096 + 4096 + t] = (gy + 1.0f) * 31.5f - h;
    }
}

// ---------------------------------------------------------------------------
// launch
// ---------------------------------------------------------------------------
extern "C" void kernel_launch(void* const* d_in, const int* in_sizes, int n_in,
                              void* d_out, int out_size)
{
    (void)in_sizes; (void)n_in; (void)out_size;
    const float* f0c = (const float*)d_in[0];
    const float* f1c = (const float*)d_in[1];
    const float* f0f = (const float*)d_in[2];
    const float* f1f = (const float*)d_in[3];
    float* out = (float*)d_out;

    cudaFuncSetAttribute(gemm_corr_kernel<4096, true>,
                         cudaFuncAttributeMaxDynamicSharedMemorySize, 50688);

    // trans_features = stack([feat0_f, feat1_f], axis=1) — single copy kernel
    tf_copy_kernel<<<512, 256>>>(f0f, f1f, out + OFF_TF);

    resize_coarse_kernel<<<512, 256>>>(f0c, f1c, out + OFF_TFC);

    gemm_corr_kernel<1024, false><<<dim3(16, 8, 2), 256, 30720>>>(f0c, f1c, nullptr, nullptr);
    interpA_kernel<<<2048, 256>>>();
    gemm_corr_kernel<4096, true><<<dim3(64, 32, 2), 256, 50688>>>(f0f, f1f, out + OFF_C, out + OFF_CF);

    softargmax_kernel<<<dim3(4096, 2, 2), 256>>>(out + OFF_C, out + OFF_CF,
                                                 out + OFF_FLOW, out + OFF_FLOWF);
}

// round 16
// speedup vs baseline: 1.3422x; 1.0237x over previous
#include <cuda_runtime.h>
#include <cstdint>

// ---------------------------------------------------------------------------
// Problem constants
//   feat0_c, feat1_c : [2,128,32,32] fp32
//   feat0_f, feat1_f : [2,128,64,64] fp32
// ---------------------------------------------------------------------------

static const size_t OFF_TF    = 0;
static const size_t OFF_TFC   = 2097152;
static const size_t OFF_C     = 4194304;
static const size_t OFF_CF    = 37748736;
static const size_t OFF_FLOW  = 71303168;
static const size_t OFF_FLOWF = 71319552;

// Scratch (device globals — no allocation allowed)
__device__ float g_cc[2 * 1024 * 1024];          // corr_c  [b][p0c][p1c]   8 MB
__device__ float g_i1[2 * 1024 * 4096];          // (u,v)-upsampled corr_c  33.5 MB (L2-resident)

// ---------------------------------------------------------------------------
// helpers
// ---------------------------------------------------------------------------
__device__ __forceinline__ uint32_t pack_bf16x2(float hi, float lo) {
    uint32_t r;
    asm("cvt.rn.bf16x2.f32 %0, %1, %2;" : "=r"(r) : "f"(hi), "f"(lo));
    return r;
}

__device__ __forceinline__ void mma_bf16(float* d, const uint32_t* a, const uint32_t* b) {
    asm volatile(
        "mma.sync.aligned.m16n8k16.row.col.f32.bf16.bf16.f32 "
        "{%0,%1,%2,%3}, {%4,%5,%6,%7}, {%8,%9}, {%0,%1,%2,%3};\n"
        : "+f"(d[0]), "+f"(d[1]), "+f"(d[2]), "+f"(d[3])
        : "r"(a[0]), "r"(a[1]), "r"(a[2]), "r"(a[3]), "r"(b[0]), "r"(b[1]));
}

__device__ __forceinline__ void ldsm_x4(uint32_t* r, uint32_t saddr) {
    asm volatile("ldmatrix.sync.aligned.m8n8.x4.shared.b16 {%0,%1,%2,%3}, [%4];"
                 : "=r"(r[0]), "=r"(r[1]), "=r"(r[2]), "=r"(r[3]) : "r"(saddr));
}

__device__ __forceinline__ void lerp_weights(int i, int& i0, int& i1, float& w) {
    float f = (float)(i * 31) / 63.0f;   // align_corners scale 31/63, exact at i=0,63
    i0 = (int)f;
    w  = f - (float)i0;
    i1 = min(i0 + 1, 31);
}

// ---------------------------------------------------------------------------
// Correlation GEMM (bf16x3, near-fp32 accuracy), 256 threads / 8 warps,
// 2 CTAs per SM. Block tile 128(m) x 64(n), warp tile 32x32, BK=16,
// mma.m16n8k16 + ldmatrix.x4, double-buffered smem.
// FUSE epilogue: c = 0.5*(rowinterp(g_i1) + corr), writes c + c_flip.
// ---------------------------------------------------------------------------
template <int MT, bool FUSE>
__global__ __launch_bounds__(256, 2)
void gemm_corr_kernel(const float* __restrict__ f0, const float* __restrict__ f1,
                      float* __restrict__ outC, float* __restrict__ outF)
{
    extern __shared__ uint32_t smemw[];

    const int b  = blockIdx.z;
    const int m0 = blockIdx.y * 128;
    const int n0 = blockIdx.x * 64;
    const float* A  = f0 + (size_t)b * 128 * MT;  // [K=128][MT]
    const float* Bg = f1 + (size_t)b * 128 * MT;

    const int tid  = threadIdx.x;
    const int warp = tid >> 5, lane = tid & 31;
    const int gid  = lane >> 2, tig = lane & 3;
    const int wm0  = (warp >> 1) * 32;           // 4 warp rows
    const int wn0  = (warp & 1) * 32;            // 2 warp cols

    float acc[2][4][4];
#pragma unroll
    for (int mi = 0; mi < 2; mi++)
#pragma unroll
        for (int j = 0; j < 4; j++)
#pragma unroll
            for (int r = 0; r < 4; r++) acc[mi][j][r] = 0.0f;

    // ---- producer mapping ----
    const int colA = tid & 127;
    const int kgA  = tid >> 7;                   // 0..1
    const int colB = tid & 63;
    const int kgB  = tid >> 6;                   // 0..3

    const uint32_t sbase = (uint32_t)__cvta_generic_to_shared(smemw);

    // ---- consumer ldmatrix row offsets (word units) ----
    const int Lm = lane & 7;
    const int mrowA = ((lane >> 3) & 1) * 8 + Lm;
    const int koffA = (lane >> 4) * 4;
    const uint32_t aoff0 = (uint32_t)((wm0 + mrowA) * 20 + koffA);
    const uint32_t aoff1 = (uint32_t)((wm0 + 16 + mrowA) * 20 + koffA);
    const int nrowB = Lm + ((lane >> 4) << 3);
    const int koffB = ((lane >> 3) & 1) * 4;
    const uint32_t boff0 = (uint32_t)(2560 + (wn0 + nrowB) * 20 + koffB);
    const uint32_t boff1 = (uint32_t)(2560 + (wn0 + 16 + nrowB) * 20 + koffB);

    float a0v0, a0v1, a0v2, a0v3;
    float a1v0, a1v1, a1v2, a1v3;
    float bv0, bv1, bv2, bv3;

#define LOAD_CHUNK(kb)                                                               \
    do {                                                                             \
        const float* Ar0 = A + (size_t)((kb) * 16 + kgA * 4) * MT + m0 + colA;       \
        const float* Ar1 = A + (size_t)((kb) * 16 + (kgA + 2) * 4) * MT + m0 + colA; \
        const float* Br  = Bg + (size_t)((kb) * 16 + kgB * 4) * MT + n0 + colB;      \
        a0v0 = Ar0[0]; a0v1 = Ar0[MT]; a0v2 = Ar0[2 * (size_t)MT]; a0v3 = Ar0[3 * (size_t)MT]; \
        a1v0 = Ar1[0]; a1v1 = Ar1[MT]; a1v2 = Ar1[2 * (size_t)MT]; a1v3 = Ar1[3 * (size_t)MT]; \
        bv0  = Br[0];  bv1  = Br[MT];  bv2  = Br[2 * (size_t)MT];  bv3  = Br[3 * (size_t)MT];  \
    } while (0)

#define PACK_STORE(base_w, v0, v1, v2, v3)                                           \
    do {                                                                             \
        uint32_t h0 = pack_bf16x2(v1, v0);                                           \
        uint32_t h1 = pack_bf16x2(v3, v2);                                           \
        uint32_t l0 = pack_bf16x2(v1 - __uint_as_float(h0 & 0xffff0000u),            \
                                  v0 - __uint_as_float(h0 << 16));                   \
        uint32_t l1 = pack_bf16x2(v3 - __uint_as_float(h1 & 0xffff0000u),            \
                                  v2 - __uint_as_float(h1 << 16));                   \
        *reinterpret_cast<uint2*>(&smemw[(base_w)])     = make_uint2(h0, h1);        \
        *reinterpret_cast<uint2*>(&smemw[(base_w) + 8]) = make_uint2(l0, l1);        \
    } while (0)

#define STORE_CHUNK(bufw)                                                            \
    do {                                                                             \
        PACK_STORE((bufw) + colA * 20 + 2 * kgA,       a0v0, a0v1, a0v2, a0v3);      \
        PACK_STORE((bufw) + colA * 20 + 2 * (kgA + 2), a1v0, a1v1, a1v2, a1v3);      \
        PACK_STORE((bufw) + 2560 + colB * 20 + 2 * kgB, bv0, bv1, bv2, bv3);         \
    } while (0)

    LOAD_CHUNK(0);
    STORE_CHUNK(0u);
    __syncthreads();

    for (int kb = 0; kb < 8; kb++) {
        if (kb < 7) LOAD_CHUNK(kb + 1);           // global prefetch (hidden by MMA)

        const uint32_t bw = (uint32_t)(kb & 1) * 3840u;
        uint32_t bh[2][4], bl[2][4];
        ldsm_x4(bh[0], sbase + (bw + boff0) * 4u);
        ldsm_x4(bl[0], sbase + (bw + boff0 + 8u) * 4u);
        ldsm_x4(bh[1], sbase + (bw + boff1) * 4u);
        ldsm_x4(bl[1], sbase + (bw + boff1 + 8u) * 4u);

#pragma unroll
        for (int mi = 0; mi < 2; mi++) {
            uint32_t ah[4], al[4];
            const uint32_t ao = (mi ? aoff1 : aoff0);
            ldsm_x4(ah, sbase + (bw + ao) * 4u);
            ldsm_x4(al, sbase + (bw + ao + 8u) * 4u);
#pragma unroll
            for (int j = 0; j < 4; j++) {
                const uint32_t* bfh = &bh[j >> 1][(j & 1) * 2];
                const uint32_t* bfl = &bl[j >> 1][(j & 1) * 2];
                mma_bf16(acc[mi][j], al, bfh);   // lo*hi
                mma_bf16(acc[mi][j], ah, bfl);   // hi*lo
                mma_bf16(acc[mi][j], ah, bfh);   // hi*hi
            }
        }

        if (kb < 7) STORE_CHUNK((uint32_t)((kb + 1) & 1) * 3840u);
        __syncthreads();
    }
#undef LOAD_CHUNK
#undef PACK_STORE
#undef STORE_CHUNK

    const float sc = 0.08838834764831845f;       // 1/sqrt(128)

    if constexpr (!FUSE) {
        // coarse: write scaled correlation to g_cc
        float* out = g_cc + (size_t)b * MT * MT;
        (void)outC; (void)outF;
#pragma unroll
        for (int mi = 0; mi < 2; mi++)
#pragma unroll
            for (int j = 0; j < 4; j++) {
                int r0 = m0 + wm0 + mi * 16 + gid;
                int cc = n0 + wn0 + j * 8 + 2 * tig;
                float2 v0 = make_float2(acc[mi][j][0] * sc, acc[mi][j][1] * sc);
                float2 v1 = make_float2(acc[mi][j][2] * sc, acc[mi][j][3] * sc);
                *reinterpret_cast<float2*>(&out[(size_t)r0 * MT + cc])       = v0;
                *reinterpret_cast<float2*>(&out[(size_t)(r0 + 8) * MT + cc]) = v1;
            }
    } else {
        // fine: c = 0.5*(rowinterp + corr), plus transposed write for c_flip
        float* S = reinterpret_cast<float*>(smemw);        // 128 x 65 (33.3 KB)
        float* Y = reinterpret_cast<float*>(smemw) + 8320; // 64 x 68  (17.4 KB)
        const size_t cb = (size_t)b * MT * MT;
        const int h0base = m0 >> 6;               // two h0 values: h0base, h0base+1

        // --- store corr into S (all 8 warps cover 128x64 disjointly) ---
#pragma unroll
        for (int mi = 0; mi < 2; mi++)
#pragma unroll
            for (int j = 0; j < 4; j++) {
                int r0  = wm0 + mi * 16 + gid;
                int col = wn0 + j * 8 + 2 * tig;
                S[r0 * 65 + col]           = acc[mi][j][0] * sc;
                S[r0 * 65 + col + 1]       = acc[mi][j][1] * sc;
                S[(r0 + 8) * 65 + col]     = acc[mi][j][2] * sc;
                S[(r0 + 8) * 65 + col + 1] = acc[mi][j][3] * sc;
            }

        // --- build Y: y-blend of g_i1 rows for 2 h0 values, 32 cx, 64 cols ---
#pragma unroll
        for (int t = 0; t < 4; t++) {
            int e     = tid + t * 256;            // 0..1023
            int h0loc = e >> 9;
            int cx    = (e >> 4) & 31;
            int c4    = e & 15;
            int y0, y1; float wy;
            lerp_weights(h0base + h0loc, y0, y1, wy);
            const float4* p0 = reinterpret_cast<const float4*>(
                g_i1 + ((size_t)b * 1024 + y0 * 32 + cx) * 4096 + n0) + c4;
            const float4* p1 = reinterpret_cast<const float4*>(
                g_i1 + ((size_t)b * 1024 + y1 * 32 + cx) * 4096 + n0) + c4;
            float4 a = *p0, bb = *p1;
            float4 v;
            v.x = a.x + wy * (bb.x - a.x);
            v.y = a.y + wy * (bb.y - a.y);
            v.z = a.z + wy * (bb.z - a.z);
            v.w = a.w + wy * (bb.w - a.w);
            *reinterpret_cast<float4*>(&Y[(h0loc * 32 + cx) * 68 + c4 * 4]) = v;
        }
        __syncthreads();

        // --- combine: x-blend + corr, write c, keep combined in S ---
#pragma unroll
        for (int q = 0; q < 8; q++) {
            int idx = tid + q * 256;              // float4 units over 128x64
            int r   = idx >> 4;
            int cf  = (idx & 15) << 2;
            int h0loc = r >> 6;
            int w0    = r & 63;
            int x0, x1; float wx;
            lerp_weights(w0, x0, x1, wx);
            float4 ya = *reinterpret_cast<const float4*>(&Y[(h0loc * 32 + x0) * 68 + cf]);
            float4 yb = *reinterpret_cast<const float4*>(&Y[(h0loc * 32 + x1) * 68 + cf]);
            float4 ip;
            ip.x = ya.x + wx * (yb.x - ya.x);
            ip.y = ya.y + wx * (yb.y - ya.y);
            ip.z = ya.z + wx * (yb.z - ya.z);
            ip.w = ya.w + wx * (yb.w - ya.w);
            size_t ga = cb + (size_t)(m0 + r) * MT + n0 + cf;
            float4 v;
            v.x = 0.5f * (ip.x + S[r * 65 + cf]);
            v.y = 0.5f * (ip.y + S[r * 65 + cf + 1]);
            v.z = 0.5f * (ip.z + S[r * 65 + cf + 2]);
            v.w = 0.5f * (ip.w + S[r * 65 + cf + 3]);
            *reinterpret_cast<float4*>(outC + ga) = v;
            S[r * 65 + cf]     = v.x;             // keep combined value for flip write
            S[r * 65 + cf + 1] = v.y;
            S[r * 65 + cf + 2] = v.z;
            S[r * 65 + cf + 3] = v.w;
        }
        __syncthreads();

        // --- transposed rows: c_flip[n][m0..m0+127] ---
#pragma unroll
        for (int jr = 0; jr < 8; jr++) {
            int n = warp * 8 + jr;
            size_t fb = cb + (size_t)(n0 + n) * MT + m0;
#pragma unroll
            for (int q = 0; q < 4; q++) {
                int m = lane + q * 32;            // bank = (m+n)%32 -> conflict-free
                outF[fb + m] = S[m * 65 + n];
            }
        }
    }
}

// ---------------------------------------------------------------------------
// trans_features copy: out[b][i][C*64*64] = stack([f0f, f1f], axis=1)
// ---------------------------------------------------------------------------
__global__ __launch_bounds__(256)
void tf_copy_kernel(const float* __restrict__ f0f, const float* __restrict__ f1f,
                    float* __restrict__ out)
{
    const size_t chunk4 = (size_t)128 * 1024;    // float4 per (b,i)
    size_t idx = (size_t)blockIdx.x * 256 + threadIdx.x;
#pragma unroll
    for (int q = 0; q < 4; q++) {
        size_t e  = idx + (size_t)q * 131072;
        size_t bi = e / chunk4;                  // 0..3 = (b<<1)|i
        size_t off = e - bi * chunk4;
        const float4* src = reinterpret_cast<const float4*>((bi & 1) ? f1f : f0f)
                          + (bi >> 1) * chunk4 + off;
        reinterpret_cast<float4*>(out)[e] = *src;
    }
}

// ---------------------------------------------------------------------------
// Separable bilinear 32->64 (align_corners) upsample body:
//   pass1: rx[y][ox] = (1-wx)*s[y,x0] + wx*s[y,x1]   (the original inner parens)
//   pass2: out[oy][ox] = (1-wy)*rx[y0][ox] + wy*rx[y1][ox]  (float4 LDS/STG)
// Operation tree identical to the fused form -> bit-identical output.
// ---------------------------------------------------------------------------
__device__ __forceinline__ void upsample_32_to_64(const float* __restrict__ in,
                                                  float* __restrict__ o, int tid)
{
    __shared__ float s[1024];
    __shared__ float rx[2048];                   // 32 x 64
    __shared__ float wT[64];
    __shared__ int   i0T[64], i1T[64];
#pragma unroll
    for (int q = 0; q < 4; q++) s[tid + q * 256] = in[tid + q * 256];
    if (tid < 64) {
        int i0, i1; float w;
        lerp_weights(tid, i0, i1, w);
        wT[tid] = w; i0T[tid] = i0; i1T[tid] = i1;
    }
    __syncthreads();
    // pass1: 2048 x-blended values
#pragma unroll
    for (int t = 0; t < 8; t++) {
        int e  = tid + t * 256;
        int y  = e >> 6, ox = e & 63;
        float wx = wT[ox];
        int x0 = i0T[ox], x1 = i1T[ox];
        rx[y * 64 + ox] = (1.0f - wx) * s[y * 32 + x0] + wx * s[y * 32 + x1];
    }
    __syncthreads();
    // pass2: y-blend, vectorized
#pragma unroll
    for (int t = 0; t < 4; t++) {
        int e  = tid + t * 256;
        int oy = e >> 4, c4 = e & 15;
        float wy = wT[oy];
        int y0 = i0T[oy], y1 = i1T[oy];
        float4 a = *reinterpret_cast<const float4*>(&rx[y0 * 64 + c4 * 4]);
        float4 b = *reinterpret_cast<const float4*>(&rx[y1 * 64 + c4 * 4]);
        float4 v;
        v.x = (1.0f - wy) * a.x + wy * b.x;
        v.y = (1.0f - wy) * a.y + wy * b.y;
        v.z = (1.0f - wy) * a.z + wy * b.z;
        v.w = (1.0f - wy) * a.w + wy * b.w;
        *reinterpret_cast<float4*>(&o[oy * 64 + c4 * 4]) = v;
    }
}

// trans_features_coarse: bilinear 32->64 per channel
__global__ __launch_bounds__(256)
void resize_coarse_kernel(const float* __restrict__ a, const float* __restrict__ bsrc,
                          float* __restrict__ out)
{
    int blk = blockIdx.x;                        // 0..511
    int bb = blk >> 8, ii = (blk >> 7) & 1, ch = blk & 127;
    const float* in = (ii ? bsrc : a) + ((size_t)bb * 128 + ch) * 1024;
    float* o = out + (((size_t)bb * 2 + ii) * 128 + ch) * 4096;
    upsample_32_to_64(in, o, threadIdx.x);
}

// interp pass A: per (b,p0c) row, upsample (u,v) 32x32 -> 64x64
__global__ __launch_bounds__(256)
void interpA_kernel()
{
    int blk = blockIdx.x;                        // 0..2047 = b*1024 + p0c
    upsample_32_to_64(g_cc + (size_t)blk * 1024, g_i1 + (size_t)blk * 4096, threadIdx.x);
}

// ---------------------------------------------------------------------------
// soft-argmax: softmax(row/0.02) over 4096 source positions, marginal means.
// Per thread: yn constant (Sy = yn*Z), xn = xn0 + e*step (Sx = xn0*Z + step*Se).
// L2-locality: iterate b=1 first, rows descending (GEMM-tail data still in L2).
// ---------------------------------------------------------------------------
__global__ __launch_bounds__(256)
void softargmax_kernel(const float* __restrict__ c0, const float* __restrict__ c1,
                       float* __restrict__ fl0, float* __restrict__ fl1)
{
    const int t  = 4095 - blockIdx.x;            // descending rows (GEMM tail first)
    const int bb = 1 - blockIdx.y;               // batch 1 first (still L2-resident)
    const float* cmat = blockIdx.z ? c1 : c0;
    float* flow       = blockIdx.z ? fl1 : fl0;
    const float* row = cmat + ((size_t)bb * 4096 + t) * 4096;
    const int tid = threadIdx.x;
    const int warp = tid >> 5, lane = tid & 31;

    float v[16];
    const float4* r4 = reinterpret_cast<const float4*>(row) + tid * 4;
#pragma unroll
    for (int q = 0; q < 4; q++) {
        float4 x = r4[q];
        v[q * 4] = x.x; v[q * 4 + 1] = x.y; v[q * 4 + 2] = x.z; v[q * 4 + 3] = x.w;
    }

    float mx = v[0];
#pragma unroll
    for (int e = 1; e < 16; e++) mx = fmaxf(mx, v[e]);
#pragma unroll
    for (int o = 16; o; o >>= 1) mx = fmaxf(mx, __shfl_xor_sync(0xffffffffu, mx, o));

    __shared__ float smax[8];
    if (lane == 0) smax[warp] = mx;
    __syncthreads();
    mx = smax[0];
#pragma unroll
    for (int i = 1; i < 8; i++) mx = fmaxf(mx, smax[i]);

    // base = 16*tid: (base&63)+e never wraps (e<16), (base+e)>>6 constant.
    const int base = tid * 16;
    const float step = 2.0f / 63.0f;
    const float xn0 = (float)((base & 63) * 2) / 63.0f - 1.0f;
    const float yn  = (float)((base >> 6) * 2) / 63.0f - 1.0f;

    float Z = 0.0f, Se = 0.0f;
#pragma unroll
    for (int e = 0; e < 16; e++) {
        float tt = (v[e] - mx) * 50.0f;           // /beta = *50
        if (tt > -25.0f) {                        // skipped terms < 1.4e-11 * Z
            float ee = __expf(tt);
            Z  += ee;
            Se += ee * (float)e;
        }
    }
    float Sx = xn0 * Z + step * Se;
    float Sy = yn * Z;
#pragma unroll
    for (int o = 16; o; o >>= 1) {
        Z  += __shfl_xor_sync(0xffffffffu, Z,  o);
        Sx += __shfl_xor_sync(0xffffffffu, Sx, o);
        Sy += __shfl_xor_sync(0xffffffffu, Sy, o);
    }
    __shared__ float sz[8], sxs[8], sys[8];
    if (lane == 0) { sz[warp] = Z; sxs[warp] = Sx; sys[warp] = Sy; }
    __syncthreads();
    if (tid == 0) {
        float z = 0.0f, X = 0.0f, Yv = 0.0f;
#pragma unroll
        for (int i = 0; i < 8; i++) { z += sz[i]; X += sxs[i]; Yv += sys[i]; }
        float gx = X / z, gy = Yv / z;
        float w = (float)(t & 63), h = (float)(t >> 6);
        flow[(size_t)bb * 2 * 4096 + t]        = (gx + 1.0f) * 31.5f - w;
        flow[(size_t)bb * 2 * 4096 + 4096 + t] = (gy + 1.0f) * 31.5f - h;
    }
}

// ---------------------------------------------------------------------------
// launch
// ---------------------------------------------------------------------------
extern "C" void kernel_launch(void* const* d_in, const int* in_sizes, int n_in,
                              void* d_out, int out_size)
{
    (void)in_sizes; (void)n_in; (void)out_size;
    const float* f0c = (const float*)d_in[0];
    const float* f1c = (const float*)d_in[1];
    const float* f0f = (const float*)d_in[2];
    const float* f1f = (const float*)d_in[3];
    float* out = (float*)d_out;

    cudaFuncSetAttribute(gemm_corr_kernel<4096, true>,
                         cudaFuncAttributeMaxDynamicSharedMemorySize, 50688);

    // trans_features = stack([feat0_f, feat1_f], axis=1) — single copy kernel
    tf_copy_kernel<<<512, 256>>>(f0f, f1f, out + OFF_TF);

    resize_coarse_kernel<<<512, 256>>>(f0c, f1c, out + OFF_TFC);

    gemm_corr_kernel<1024, false><<<dim3(16, 8, 2), 256, 30720>>>(f0c, f1c, nullptr, nullptr);
    interpA_kernel<<<2048, 256>>>();
    gemm_corr_kernel<4096, true><<<dim3(64, 32, 2), 256, 50688>>>(f0f, f1f, out + OFF_C, out + OFF_CF);

    softargmax_kernel<<<dim3(4096, 2, 2), 256>>>(out + OFF_C, out + OFF_CF,
                                                 out + OFF_FLOW, out + OFF_FLOWF);
}

// round 17
// speedup vs baseline: 1.3495x; 1.0054x over previous
#include <cuda_runtime.h>
#include <cstdint>

// ---------------------------------------------------------------------------
// Problem constants
//   feat0_c, feat1_c : [2,128,32,32] fp32
//   feat0_f, feat1_f : [2,128,64,64] fp32
// ---------------------------------------------------------------------------

static const size_t OFF_TF    = 0;
static const size_t OFF_TFC   = 2097152;
static const size_t OFF_C     = 4194304;
static const size_t OFF_CF    = 37748736;
static const size_t OFF_FLOW  = 71303168;
static const size_t OFF_FLOWF = 71319552;

// Scratch (device globals — no allocation allowed)
__device__ float g_cc[2 * 1024 * 1024];          // corr_c  [b][p0c][p1c]   8 MB
__device__ float g_i1[2 * 1024 * 2048];          // x-blended corr_c [b][p0c][u][w1]  16.7 MB (L2-resident)

// ---------------------------------------------------------------------------
// helpers
// ---------------------------------------------------------------------------
__device__ __forceinline__ uint32_t pack_bf16x2(float hi, float lo) {
    uint32_t r;
    asm("cvt.rn.bf16x2.f32 %0, %1, %2;" : "=r"(r) : "f"(hi), "f"(lo));
    return r;
}

__device__ __forceinline__ void mma_bf16(float* d, const uint32_t* a, const uint32_t* b) {
    asm volatile(
        "mma.sync.aligned.m16n8k16.row.col.f32.bf16.bf16.f32 "
        "{%0,%1,%2,%3}, {%4,%5,%6,%7}, {%8,%9}, {%0,%1,%2,%3};\n"
        : "+f"(d[0]), "+f"(d[1]), "+f"(d[2]), "+f"(d[3])
        : "r"(a[0]), "r"(a[1]), "r"(a[2]), "r"(a[3]), "r"(b[0]), "r"(b[1]));
}

__device__ __forceinline__ void ldsm_x4(uint32_t* r, uint32_t saddr) {
    asm volatile("ldmatrix.sync.aligned.m8n8.x4.shared.b16 {%0,%1,%2,%3}, [%4];"
                 : "=r"(r[0]), "=r"(r[1]), "=r"(r[2]), "=r"(r[3]) : "r"(saddr));
}

__device__ __forceinline__ void lerp_weights(int i, int& i0, int& i1, float& w) {
    float f = (float)(i * 31) / 63.0f;   // align_corners scale 31/63, exact at i=0,63
    i0 = (int)f;
    w  = f - (float)i0;
    i1 = min(i0 + 1, 31);
}

// ---------------------------------------------------------------------------
// Correlation GEMM (bf16x3, near-fp32 accuracy), 256 threads / 8 warps,
// 2 CTAs per SM. Block tile 128(m) x 64(n), warp tile 32x32, BK=16,
// mma.m16n8k16 + ldmatrix.x4, double-buffered smem.
// FUSE epilogue: c = 0.5*(interp + corr), writes c + c_flip. The interp
// now includes the u->h1 blend (pass2 of the separable upsample), applied
// bit-identically to the former interpA pass2 + Y-build lerp.
// ---------------------------------------------------------------------------
template <int MT, bool FUSE>
__global__ __launch_bounds__(256, 2)
void gemm_corr_kernel(const float* __restrict__ f0, const float* __restrict__ f1,
                      float* __restrict__ outC, float* __restrict__ outF)
{
    extern __shared__ uint32_t smemw[];

    const int b  = blockIdx.z;
    const int m0 = blockIdx.y * 128;
    const int n0 = blockIdx.x * 64;
    const float* A  = f0 + (size_t)b * 128 * MT;  // [K=128][MT]
    const float* Bg = f1 + (size_t)b * 128 * MT;

    const int tid  = threadIdx.x;
    const int warp = tid >> 5, lane = tid & 31;
    const int gid  = lane >> 2, tig = lane & 3;
    const int wm0  = (warp >> 1) * 32;           // 4 warp rows
    const int wn0  = (warp & 1) * 32;            // 2 warp cols

    float acc[2][4][4];
#pragma unroll
    for (int mi = 0; mi < 2; mi++)
#pragma unroll
        for (int j = 0; j < 4; j++)
#pragma unroll
            for (int r = 0; r < 4; r++) acc[mi][j][r] = 0.0f;

    // ---- producer mapping ----
    const int colA = tid & 127;
    const int kgA  = tid >> 7;                   // 0..1
    const int colB = tid & 63;
    const int kgB  = tid >> 6;                   // 0..3

    const uint32_t sbase = (uint32_t)__cvta_generic_to_shared(smemw);

    // ---- consumer ldmatrix row offsets (word units) ----
    const int Lm = lane & 7;
    const int mrowA = ((lane >> 3) & 1) * 8 + Lm;
    const int koffA = (lane >> 4) * 4;
    const uint32_t aoff0 = (uint32_t)((wm0 + mrowA) * 20 + koffA);
    const uint32_t aoff1 = (uint32_t)((wm0 + 16 + mrowA) * 20 + koffA);
    const int nrowB = Lm + ((lane >> 4) << 3);
    const int koffB = ((lane >> 3) & 1) * 4;
    const uint32_t boff0 = (uint32_t)(2560 + (wn0 + nrowB) * 20 + koffB);
    const uint32_t boff1 = (uint32_t)(2560 + (wn0 + 16 + nrowB) * 20 + koffB);

    float a0v0, a0v1, a0v2, a0v3;
    float a1v0, a1v1, a1v2, a1v3;
    float bv0, bv1, bv2, bv3;

#define LOAD_CHUNK(kb)                                                               \
    do {                                                                             \
        const float* Ar0 = A + (size_t)((kb) * 16 + kgA * 4) * MT + m0 + colA;       \
        const float* Ar1 = A + (size_t)((kb) * 16 + (kgA + 2) * 4) * MT + m0 + colA; \
        const float* Br  = Bg + (size_t)((kb) * 16 + kgB * 4) * MT + n0 + colB;      \
        a0v0 = Ar0[0]; a0v1 = Ar0[MT]; a0v2 = Ar0[2 * (size_t)MT]; a0v3 = Ar0[3 * (size_t)MT]; \
        a1v0 = Ar1[0]; a1v1 = Ar1[MT]; a1v2 = Ar1[2 * (size_t)MT]; a1v3 = Ar1[3 * (size_t)MT]; \
        bv0  = Br[0];  bv1  = Br[MT];  bv2  = Br[2 * (size_t)MT];  bv3  = Br[3 * (size_t)MT];  \
    } while (0)

#define PACK_STORE(base_w, v0, v1, v2, v3)                                           \
    do {                                                                             \
        uint32_t h0 = pack_bf16x2(v1, v0);                                           \
        uint32_t h1 = pack_bf16x2(v3, v2);                                           \
        uint32_t l0 = pack_bf16x2(v1 - __uint_as_float(h0 & 0xffff0000u),            \
                                  v0 - __uint_as_float(h0 << 16));                   \
        uint32_t l1 = pack_bf16x2(v3 - __uint_as_float(h1 & 0xffff0000u),            \
                                  v2 - __uint_as_float(h1 << 16));                   \
        *reinterpret_cast<uint2*>(&smemw[(base_w)])     = make_uint2(h0, h1);        \
        *reinterpret_cast<uint2*>(&smemw[(base_w) + 8]) = make_uint2(l0, l1);        \
    } while (0)

#define STORE_CHUNK(bufw)                                                            \
    do {                                                                             \
        PACK_STORE((bufw) + colA * 20 + 2 * kgA,       a0v0, a0v1, a0v2, a0v3);      \
        PACK_STORE((bufw) + colA * 20 + 2 * (kgA + 2), a1v0, a1v1, a1v2, a1v3);      \
        PACK_STORE((bufw) + 2560 + colB * 20 + 2 * kgB, bv0, bv1, bv2, bv3);         \
    } while (0)

    LOAD_CHUNK(0);
    STORE_CHUNK(0u);
    __syncthreads();

    for (int kb = 0; kb < 8; kb++) {
        if (kb < 7) LOAD_CHUNK(kb + 1);           // global prefetch (hidden by MMA)

        const uint32_t bw = (uint32_t)(kb & 1) * 3840u;
        uint32_t bh[2][4], bl[2][4];
        ldsm_x4(bh[0], sbase + (bw + boff0) * 4u);
        ldsm_x4(bl[0], sbase + (bw + boff0 + 8u) * 4u);
        ldsm_x4(bh[1], sbase + (bw + boff1) * 4u);
        ldsm_x4(bl[1], sbase + (bw + boff1 + 8u) * 4u);

#pragma unroll
        for (int mi = 0; mi < 2; mi++) {
            uint32_t ah[4], al[4];
            const uint32_t ao = (mi ? aoff1 : aoff0);
            ldsm_x4(ah, sbase + (bw + ao) * 4u);
            ldsm_x4(al, sbase + (bw + ao + 8u) * 4u);
#pragma unroll
            for (int j = 0; j < 4; j++) {
                const uint32_t* bfh = &bh[j >> 1][(j & 1) * 2];
                const uint32_t* bfl = &bl[j >> 1][(j & 1) * 2];
                mma_bf16(acc[mi][j], al, bfh);   // lo*hi
                mma_bf16(acc[mi][j], ah, bfl);   // hi*lo
                mma_bf16(acc[mi][j], ah, bfh);   // hi*hi
            }
        }

        if (kb < 7) STORE_CHUNK((uint32_t)((kb + 1) & 1) * 3840u);
        __syncthreads();
    }
#undef LOAD_CHUNK
#undef PACK_STORE
#undef STORE_CHUNK

    const float sc = 0.08838834764831845f;       // 1/sqrt(128)

    if constexpr (!FUSE) {
        // coarse: write scaled correlation to g_cc
        float* out = g_cc + (size_t)b * MT * MT;
        (void)outC; (void)outF;
#pragma unroll
        for (int mi = 0; mi < 2; mi++)
#pragma unroll
            for (int j = 0; j < 4; j++) {
                int r0 = m0 + wm0 + mi * 16 + gid;
                int cc = n0 + wn0 + j * 8 + 2 * tig;
                float2 v0 = make_float2(acc[mi][j][0] * sc, acc[mi][j][1] * sc);
                float2 v1 = make_float2(acc[mi][j][2] * sc, acc[mi][j][3] * sc);
                *reinterpret_cast<float2*>(&out[(size_t)r0 * MT + cc])       = v0;
                *reinterpret_cast<float2*>(&out[(size_t)(r0 + 8) * MT + cc]) = v1;
            }
    } else {
        // fine: c = 0.5*(interp + corr), plus transposed write for c_flip
        float* S = reinterpret_cast<float*>(smemw);        // 128 x 65 (33.3 KB)
        float* Y = reinterpret_cast<float*>(smemw) + 8320; // 64 x 68  (17.4 KB)
        const size_t cb = (size_t)b * MT * MT;
        const int h0base = m0 >> 6;               // two h0 values: h0base, h0base+1
        const int h1 = n0 >> 6;                   // block-constant target h1
        int u0, u1; float wu;
        lerp_weights(h1, u0, u1, wu);             // pass2 weights (u -> h1)

        // --- store corr into S (all 8 warps cover 128x64 disjointly) ---
#pragma unroll
        for (int mi = 0; mi < 2; mi++)
#pragma unroll
            for (int j = 0; j < 4; j++) {
                int r0  = wm0 + mi * 16 + gid;
                int col = wn0 + j * 8 + 2 * tig;
                S[r0 * 65 + col]           = acc[mi][j][0] * sc;
                S[r0 * 65 + col + 1]       = acc[mi][j][1] * sc;
                S[(r0 + 8) * 65 + col]     = acc[mi][j][2] * sc;
                S[(r0 + 8) * 65 + col + 1] = acc[mi][j][3] * sc;
            }

        // --- build Y: pass2 u-blend (bit-identical to old interpA pass2) then
        //     y-blend over h0 (bit-identical to old Y-build lerp) ---
#pragma unroll
        for (int t = 0; t < 4; t++) {
            int e     = tid + t * 256;            // 0..1023
            int h0loc = e >> 9;
            int cx    = (e >> 4) & 31;
            int c4    = e & 15;
            int y0, y1; float wy;
            lerp_weights(h0base + h0loc, y0, y1, wy);
            const float4* r0p = reinterpret_cast<const float4*>(
                g_i1 + ((size_t)b * 1024 + y0 * 32 + cx) * 2048) + c4;
            const float4* r1p = reinterpret_cast<const float4*>(
                g_i1 + ((size_t)b * 1024 + y1 * 32 + cx) * 2048) + c4;
            float4 v00 = r0p[u0 * 16], v01 = r0p[u1 * 16];
            float4 v10 = r1p[u0 * 16], v11 = r1p[u1 * 16];
            float4 a, bb;                          // pass2: (1-wu)*lo + wu*hi
            a.x = (1.0f - wu) * v00.x + wu * v01.x;
            a.y = (1.0f - wu) * v00.y + wu * v01.y;
            a.z = (1.0f - wu) * v00.z + wu * v01.z;
            a.w = (1.0f - wu) * v00.w + wu * v01.w;
            bb.x = (1.0f - wu) * v10.x + wu * v11.x;
            bb.y = (1.0f - wu) * v10.y + wu * v11.y;
            bb.z = (1.0f - wu) * v10.z + wu * v11.z;
            bb.w = (1.0f - wu) * v10.w + wu * v11.w;
            float4 v;
            v.x = a.x + wy * (bb.x - a.x);
            v.y = a.y + wy * (bb.y - a.y);
            v.z = a.z + wy * (bb.z - a.z);
            v.w = a.w + wy * (bb.w - a.w);
            *reinterpret_cast<float4*>(&Y[(h0loc * 32 + cx) * 68 + c4 * 4]) = v;
        }
        __syncthreads();

        // --- combine: x-blend + corr, write c, keep combined in S ---
#pragma unroll
        for (int q = 0; q < 8; q++) {
            int idx = tid + q * 256;              // float4 units over 128x64
            int r   = idx >> 4;
            int cf  = (idx & 15) << 2;
            int h0loc = r >> 6;
            int w0    = r & 63;
            int x0, x1; float wx;
            lerp_weights(w0, x0, x1, wx);
            float4 ya = *reinterpret_cast<const float4*>(&Y[(h0loc * 32 + x0) * 68 + cf]);
            float4 yb = *reinterpret_cast<const float4*>(&Y[(h0loc * 32 + x1) * 68 + cf]);
            float4 ip;
            ip.x = ya.x + wx * (yb.x - ya.x);
            ip.y = ya.y + wx * (yb.y - ya.y);
            ip.z = ya.z + wx * (yb.z - ya.z);
            ip.w = ya.w + wx * (yb.w - ya.w);
            size_t ga = cb + (size_t)(m0 + r) * MT + n0 + cf;
            float4 v;
            v.x = 0.5f * (ip.x + S[r * 65 + cf]);
            v.y = 0.5f * (ip.y + S[r * 65 + cf + 1]);
            v.z = 0.5f * (ip.z + S[r * 65 + cf + 2]);
            v.w = 0.5f * (ip.w + S[r * 65 + cf + 3]);
            *reinterpret_cast<float4*>(outC + ga) = v;
            S[r * 65 + cf]     = v.x;             // keep combined value for flip write
            S[r * 65 + cf + 1] = v.y;
            S[r * 65 + cf + 2] = v.z;
            S[r * 65 + cf + 3] = v.w;
        }
        __syncthreads();

        // --- transposed rows: c_flip[n][m0..m0+127] ---
#pragma unroll
        for (int jr = 0; jr < 8; jr++) {
            int n = warp * 8 + jr;
            size_t fb = cb + (size_t)(n0 + n) * MT + m0;
#pragma unroll
            for (int q = 0; q < 4; q++) {
                int m = lane + q * 32;            // bank = (m+n)%32 -> conflict-free
                outF[fb + m] = S[m * 65 + n];
            }
        }
    }
}

// ---------------------------------------------------------------------------
// Separable bilinear 32->64 (align_corners) upsample, both passes (for
// trans_features_coarse, whose output is final). Bit-identical to original.
// ---------------------------------------------------------------------------
__device__ __forceinline__ void upsample_32_to_64(const float* __restrict__ in,
                                                  float* __restrict__ o, int tid)
{
    __shared__ float s[1024];
    __shared__ float rx[2048];                   // 32 x 64
    __shared__ float wT[64];
    __shared__ int   i0T[64], i1T[64];
#pragma unroll
    for (int q = 0; q < 4; q++) s[tid + q * 256] = in[tid + q * 256];
    if (tid < 64) {
        int i0, i1; float w;
        lerp_weights(tid, i0, i1, w);
        wT[tid] = w; i0T[tid] = i0; i1T[tid] = i1;
    }
    __syncthreads();
#pragma unroll
    for (int t = 0; t < 8; t++) {
        int e  = tid + t * 256;
        int y  = e >> 6, ox = e & 63;
        float wx = wT[ox];
        int x0 = i0T[ox], x1 = i1T[ox];
        rx[y * 64 + ox] = (1.0f - wx) * s[y * 32 + x0] + wx * s[y * 32 + x1];
    }
    __syncthreads();
#pragma unroll
    for (int t = 0; t < 4; t++) {
        int e  = tid + t * 256;
        int oy = e >> 4, c4 = e & 15;
        float wy = wT[oy];
        int y0 = i0T[oy], y1 = i1T[oy];
        float4 a = *reinterpret_cast<const float4*>(&rx[y0 * 64 + c4 * 4]);
        float4 b = *reinterpret_cast<const float4*>(&rx[y1 * 64 + c4 * 4]);
        float4 v;
        v.x = (1.0f - wy) * a.x + wy * b.x;
        v.y = (1.0f - wy) * a.y + wy * b.y;
        v.z = (1.0f - wy) * a.z + wy * b.z;
        v.w = (1.0f - wy) * a.w + wy * b.w;
        *reinterpret_cast<float4*>(&o[oy * 64 + c4 * 4]) = v;
    }
}

// ---------------------------------------------------------------------------
// misc kernel: blocks 0-511 tf_copy, 512-1023 resize_coarse (independent work)
// ---------------------------------------------------------------------------
__global__ __launch_bounds__(256)
void misc_kernel(const float* __restrict__ f0f, const float* __restrict__ f1f,
                 const float* __restrict__ f0c, const float* __restrict__ f1c,
                 float* __restrict__ outTF, float* __restrict__ outTFC)
{
    const int tid = threadIdx.x;
    if (blockIdx.x < 512) {
        // trans_features = stack([feat0_f, feat1_f], axis=1)
        const size_t chunk4 = (size_t)128 * 1024;    // float4 per (b,i)
        size_t idx = (size_t)blockIdx.x * 256 + tid;
#pragma unroll
        for (int q = 0; q < 4; q++) {
            size_t e  = idx + (size_t)q * 131072;
            size_t bi = e / chunk4;                  // 0..3 = (b<<1)|i
            size_t off = e - bi * chunk4;
            const float4* src = reinterpret_cast<const float4*>((bi & 1) ? f1f : f0f)
                              + (bi >> 1) * chunk4 + off;
            reinterpret_cast<float4*>(outTF)[e] = *src;
        }
    } else {
        int blk = blockIdx.x - 512;                  // 0..511
        int bb = blk >> 8, ii = (blk >> 7) & 1, ch = blk & 127;
        const float* in = (ii ? f1c : f0c) + ((size_t)bb * 128 + ch) * 1024;
        float* o = outTFC + (((size_t)bb * 2 + ii) * 128 + ch) * 4096;
        upsample_32_to_64(in, o, tid);
    }
}

// ---------------------------------------------------------------------------
// interp pass A (x-blend ONLY): g_i1h[b][p0c][u][w1] = pass1 of the upsample.
// Pass2 (u->h1) moved into the fine-GEMM epilogue (bit-identical there).
// ---------------------------------------------------------------------------
__global__ __launch_bounds__(256)
void interpA_kernel()
{
    __shared__ float s[1024];
    __shared__ float wT[64];
    __shared__ int   i0T[64], i1T[64];
    int blk = blockIdx.x;                        // 0..2047 = b*1024 + p0c
    const float* in = g_cc + (size_t)blk * 1024;
    float* o = g_i1 + (size_t)blk * 2048;
    int tid = threadIdx.x;
#pragma unroll
    for (int q = 0; q < 4; q++) s[tid + q * 256] = in[tid + q * 256];
    if (tid < 64) {
        int i0, i1; float w;
        lerp_weights(tid, i0, i1, w);
        wT[tid] = w; i0T[tid] = i0; i1T[tid] = i1;
    }
    __syncthreads();
#pragma unroll
    for (int t = 0; t < 8; t++) {
        int e  = tid + t * 256;
        int u  = e >> 6, ox = e & 63;
        float wx = wT[ox];
        int x0 = i0T[ox], x1 = i1T[ox];
        o[e] = (1.0f - wx) * s[u * 32 + x0] + wx * s[u * 32 + x1];
    }
}

// ---------------------------------------------------------------------------
// soft-argmax: softmax(row/0.02) over 4096 source positions, marginal means.
// Per thread: yn constant (Sy = yn*Z), xn = xn0 + e*step (Sx = xn0*Z + step*Se).
// L2-locality: iterate b=1 first, rows descending (GEMM-tail data still in L2).
// ---------------------------------------------------------------------------
__global__ __launch_bounds__(256)
void softargmax_kernel(const float* __restrict__ c0, const float* __restrict__ c1,
                       float* __restrict__ fl0, float* __restrict__ fl1)
{
    const int t  = 4095 - blockIdx.x;            // descending rows (GEMM tail first)
    const int bb = 1 - blockIdx.y;               // batch 1 first (still L2-resident)
    const float* cmat = blockIdx.z ? c1 : c0;
    float* flow       = blockIdx.z ? fl1 : fl0;
    const float* row = cmat + ((size_t)bb * 4096 + t) * 4096;
    const int tid = threadIdx.x;
    const int warp = tid >> 5, lane = tid & 31;

    float v[16];
    const float4* r4 = reinterpret_cast<const float4*>(row) + tid * 4;
#pragma unroll
    for (int q = 0; q < 4; q++) {
        float4 x = r4[q];
        v[q * 4] = x.x; v[q * 4 + 1] = x.y; v[q * 4 + 2] = x.z; v[q * 4 + 3] = x.w;
    }

    float mx = v[0];
#pragma unroll
    for (int e = 1; e < 16; e++) mx = fmaxf(mx, v[e]);
#pragma unroll
    for (int o = 16; o; o >>= 1) mx = fmaxf(mx, __shfl_xor_sync(0xffffffffu, mx, o));

    __shared__ float smax[8];
    if (lane == 0) smax[warp] = mx;
    __syncthreads();
    mx = smax[0];
#pragma unroll
    for (int i = 1; i < 8; i++) mx = fmaxf(mx, smax[i]);

    const int base = tid * 16;
    const float step = 2.0f / 63.0f;
    const float xn0 = (float)((base & 63) * 2) / 63.0f - 1.0f;
    const float yn  = (float)((base >> 6) * 2) / 63.0f - 1.0f;

    float Z = 0.0f, Se = 0.0f;
#pragma unroll
    for (int e = 0; e < 16; e++) {
        float tt = (v[e] - mx) * 50.0f;           // /beta = *50
        if (tt > -25.0f) {                        // skipped terms < 1.4e-11 * Z
            float ee = __expf(tt);
            Z  += ee;
            Se += ee * (float)e;
        }
    }
    float Sx = xn0 * Z + step * Se;
    float Sy = yn * Z;
#pragma unroll
    for (int o = 16; o; o >>= 1) {
        Z  += __shfl_xor_sync(0xffffffffu, Z,  o);
        Sx += __shfl_xor_sync(0xffffffffu, Sx, o);
        Sy += __shfl_xor_sync(0xffffffffu, Sy, o);
    }
    __shared__ float sz[8], sxs[8], sys[8];
    if (lane == 0) { sz[warp] = Z; sxs[warp] = Sx; sys[warp] = Sy; }
    __syncthreads();
    if (tid == 0) {
        float z = 0.0f, X = 0.0f, Yv = 0.0f;
#pragma unroll
        for (int i = 0; i < 8; i++) { z += sz[i]; X += sxs[i]; Yv += sys[i]; }
        float gx = X / z, gy = Yv / z;
        float w = (float)(t & 63), h = (float)(t >> 6);
        flow[(size_t)bb * 2 * 4096 + t]        = (gx + 1.0f) * 31.5f - w;
        flow[(size_t)bb * 2 * 4096 + 4096 + t] = (gy + 1.0f) * 31.5f - h;
    }
}

// ---------------------------------------------------------------------------
// launch
// ---------------------------------------------------------------------------
extern "C" void kernel_launch(void* const* d_in, const int* in_sizes, int n_in,
                              void* d_out, int out_size)
{
    (void)in_sizes; (void)n_in; (void)out_size;
    const float* f0c = (const float*)d_in[0];
    const float* f1c = (const float*)d_in[1];
    const float* f0f = (const float*)d_in[2];
    const float* f1f = (const float*)d_in[3];
    float* out = (float*)d_out;

    cudaFuncSetAttribute(gemm_corr_kernel<4096, true>,
                         cudaFuncAttributeMaxDynamicSharedMemorySize, 50688);

    misc_kernel<<<1024, 256>>>(f0f, f1f, f0c, f1c, out + OFF_TF, out + OFF_TFC);

    gemm_corr_kernel<1024, false><<<dim3(16, 8, 2), 256, 30720>>>(f0c, f1c, nullptr, nullptr);
    interpA_kernel<<<2048, 256>>>();
    gemm_corr_kernel<4096, true><<<dim3(64, 32, 2), 256, 50688>>>(f0f, f1f, out + OFF_C, out + OFF_CF);

    softargmax_kernel<<<dim3(4096, 2, 2), 256>>>(out + OFF_C, out + OFF_CF,
                                                 out + OFF_FLOW, out + OFF_FLOWF);
}